// round 6
// baseline (speedup 1.0000x reference)
#include <cuda_runtime.h>
#include <cuda_bf16.h>

#define T_N 1024
#define C_N 768
#define H_N 12
#define D_N 64
#define NT_N 8
#define LOG2E 1.4426950408889634f

// ---------------- scratch (static device globals; no allocation) ----------------
__device__ float g_q[H_N * T_N * D_N];       // [H][T][D]
__device__ float g_k[H_N * T_N * D_N];
__device__ float g_v[H_N * T_N * D_N];
__device__ float g_g[H_N * T_N * D_N];       // raw then rmsnormed+tf32-quantized g
__device__ float g_g2[H_N * T_N];            // ||ghat||^2 per (h,t)
__device__ float g_y[T_N * C_N];             // attention out, [T][C] layout

// split-j partials: 40 units per head (chunks of <=4 j-tiles)
__device__ float g_pacc[H_N * 40 * 64 * 64]; // [h][unit][row][col]
__device__ float g_pm[H_N * 40 * 64];
__device__ float g_pl[H_N * 40 * 64];
__device__ float g_dw[H_N * 16 * 64];        // diag weights per (h,it,row)

// unit tables: heavy (4-tile) units first for scheduling
__constant__ int c_uit[40] = {15,15,15,15,14,14,14,13,13,13,12,12,12,11,11,11,10,10,9,9,8,8,7,7,6,5,4,3,
                              14,10,6,2, 13,9,5,1, 12,8,4,0};
__constant__ int c_uc[40]  = { 0, 1, 2, 3, 0, 1, 2, 0, 1, 2, 0, 1, 2, 0, 1, 2, 0, 1,0,1,0,1,0,1,0,0,0,0,
                               3, 2,1,0,  3,2,1,0,  3,2,1,0};
__constant__ int c_off[16] = {0,1,2,3,4,6,8,10,12,15,18,21,24,28,32,36};

struct Consts {
    float inv4tau[H_N][NT_N];
    float wte[H_N][NT_N];
    float neghb[H_N];
    float dpl[H_N];           // lam * dp_scale/(8*0.8)
    float glk[H_N];           // (1-lam) * logk_scale * ln2
    float outs[H_N];
    float fA[H_N], fB[H_N], i4t0[H_N];
    int   fastf[H_N];
    float alpha;
};
__device__ Consts g_c;

__device__ __forceinline__ float ex2f_(float x){ float y; asm("ex2.approx.ftz.f32 %0, %1;":"=f"(y):"f"(x)); return y; }
__device__ __forceinline__ float lg2f_(float x){ float y; asm("lg2.approx.ftz.f32 %0, %1;":"=f"(y):"f"(x)); return y; }
__device__ __forceinline__ unsigned f2tf32(float x){ unsigned y; asm("cvt.rna.tf32.f32 %0, %1;":"=r"(y):"f"(x)); return y; }

__device__ __forceinline__ void mma_tf32(float* d, const unsigned* a, const unsigned* b) {
    asm volatile(
      "mma.sync.aligned.m16n8k8.row.col.f32.tf32.tf32.f32 "
      "{%0,%1,%2,%3}, {%4,%5,%6,%7}, {%8,%9}, {%0,%1,%2,%3};\n"
      : "+f"(d[0]), "+f"(d[1]), "+f"(d[2]), "+f"(d[3])
      : "r"(a[0]), "r"(a[1]), "r"(a[2]), "r"(a[3]), "r"(b[0]), "r"(b[1]));
}

// ---------------- constants precompute ----------------
__global__ void const_kernel(const float* lam_p, const float* log_tau,
                             const float* logit_w, const float* beta,
                             const float* out_scale, const float* dp_scale,
                             const float* logk_scale, const float* dt_logit) {
    if (threadIdx.x != 0 || blockIdx.x != 0) return;
    float lam = lam_p[0];
    for (int h = 0; h < H_N; ++h) {
        float mx = -1e30f;
        for (int t = 0; t < NT_N; ++t) mx = fmaxf(mx, logit_w[h*NT_N+t]);
        float s = 0.f, e[NT_N];
        for (int t = 0; t < NT_N; ++t) { e[t] = expf(logit_w[h*NT_N+t]-mx); s += e[t]; }
        float W = 0.f;
        for (int t = 0; t < NT_N; ++t) { g_c.wte[h][t] = e[t]/s + 1e-12f; W += g_c.wte[h][t]; }
        for (int t = 0; t < NT_N; ++t) {
            float tau = fmaxf(expf(log_tau[h*NT_N+t]), 1e-6f);
            g_c.inv4tau[h][t] = 1.f/(4.f*tau);
        }
        float bc = fminf(fmaxf(beta[h], 0.5f), 2.5f);
        float neghb = -0.5f*bc;
        float dpc = dp_scale[h]/(8.0f*0.8f);
        float lks = logk_scale[h]*0.6931471805599453f;
        g_c.neghb[h] = neghb;
        g_c.dpl[h]   = lam*dpc;
        g_c.glk[h]   = (1.f-lam)*lks;
        g_c.outs[h]  = out_scale[h];
        int same = 1;
        for (int t = 1; t < NT_N; ++t) if (g_c.inv4tau[h][t] != g_c.inv4tau[h][0]) same = 0;
        g_c.fastf[h] = same;
        g_c.i4t0[h]  = g_c.inv4tau[h][0];
        g_c.fA[h]    = g_c.glk[h]*neghb;
        g_c.fB[h]    = g_c.glk[h]*log2f(W);
    }
    g_c.alpha = 0.1f/(1.f+expf(-dt_logit[0]));
}

// ---------------- tf32 GEMM 128x128, double-buffered; optional qkvg scatter ----------------
#define GS 36
#define STG128 (2*128*GS)   // words per stage (A tile + B tile)

__global__ __launch_bounds__(256, 2) void gemm_tf32_128(const float* __restrict__ A,
        const float* __restrict__ B, float* __restrict__ C, int M, int N, int K, int scatter) {
    extern __shared__ unsigned gsm[];
    int tid = threadIdx.x;
    int lane = tid & 31, w = tid >> 5;
    int wm = w >> 2, wn = w & 3;
    int m0 = blockIdx.y*128, n0 = blockIdx.x*128;
    int lr = tid >> 3, lc = (tid & 7)*4;
    const float* Ap = A + (size_t)(m0+lr)*K + lc;
    const float* Bp = B + (size_t)(n0+lr)*K + lc;

    float acc[4][4][4];
    #pragma unroll
    for (int i = 0; i < 4; ++i)
        #pragma unroll
        for (int j = 0; j < 4; ++j)
            #pragma unroll
            for (int v = 0; v < 4; ++v) acc[i][j][v] = 0.f;

    int qa = lane >> 2, ra = lane & 3;

    float4 pra[4], prb[4];
    #pragma unroll
    for (int p = 0; p < 4; ++p) {
        pra[p] = *(const float4*)(Ap + (size_t)p*32*K);
        prb[p] = *(const float4*)(Bp + (size_t)p*32*K);
    }
    {   // store stage 0
        unsigned* As = gsm;
        unsigned* Bs = gsm + 128*GS;
        #pragma unroll
        for (int p = 0; p < 4; ++p) {
            unsigned* as = As + (lr + p*32)*GS + lc;
            unsigned* bs = Bs + (lr + p*32)*GS + lc;
            as[0]=f2tf32(pra[p].x); as[1]=f2tf32(pra[p].y); as[2]=f2tf32(pra[p].z); as[3]=f2tf32(pra[p].w);
            bs[0]=f2tf32(prb[p].x); bs[1]=f2tf32(prb[p].y); bs[2]=f2tf32(prb[p].z); bs[3]=f2tf32(prb[p].w);
        }
    }
    __syncthreads();
    int cur = 0;

    for (int kb = 0; kb < K; kb += 32) {
        bool nxt = (kb + 32 < K);
        if (nxt) {
            #pragma unroll
            for (int p = 0; p < 4; ++p) {
                pra[p] = *(const float4*)(Ap + (size_t)p*32*K + kb + 32);
                prb[p] = *(const float4*)(Bp + (size_t)p*32*K + kb + 32);
            }
        }
        unsigned* As = gsm + cur*STG128;
        unsigned* Bs = As + 128*GS;
        #pragma unroll
        for (int ks = 0; ks < 4; ++ks) {
            unsigned af[4][4], bf[4][2];
            #pragma unroll
            for (int mt = 0; mt < 4; ++mt) {
                const unsigned* p = As + (wm*64 + mt*16 + qa)*GS + ks*8 + ra;
                af[mt][0] = p[0];
                af[mt][1] = p[8*GS];
                af[mt][2] = p[4];
                af[mt][3] = p[8*GS + 4];
            }
            #pragma unroll
            for (int nt = 0; nt < 4; ++nt) {
                const unsigned* p = Bs + (wn*32 + nt*8 + qa)*GS + ks*8 + ra;
                bf[nt][0] = p[0];
                bf[nt][1] = p[4];
            }
            #pragma unroll
            for (int mt = 0; mt < 4; ++mt)
                #pragma unroll
                for (int nt = 0; nt < 4; ++nt)
                    mma_tf32(acc[mt][nt], af[mt], bf[nt]);
        }
        if (nxt) {
            unsigned* As2 = gsm + (cur^1)*STG128;
            unsigned* Bs2 = As2 + 128*GS;
            #pragma unroll
            for (int p = 0; p < 4; ++p) {
                unsigned* as = As2 + (lr + p*32)*GS + lc;
                unsigned* bs = Bs2 + (lr + p*32)*GS + lc;
                as[0]=f2tf32(pra[p].x); as[1]=f2tf32(pra[p].y); as[2]=f2tf32(pra[p].z); as[3]=f2tf32(pra[p].w);
                bs[0]=f2tf32(prb[p].x); bs[1]=f2tf32(prb[p].y); bs[2]=f2tf32(prb[p].z); bs[3]=f2tf32(prb[p].w);
            }
            __syncthreads();
            cur ^= 1;
        }
    }

    #pragma unroll
    for (int mt = 0; mt < 4; ++mt) {
        int row = m0 + wm*64 + mt*16 + qa;
        #pragma unroll
        for (int nt = 0; nt < 4; ++nt) {
            float2 c0 = {acc[mt][nt][0], acc[mt][nt][1]};
            float2 c1 = {acc[mt][nt][2], acc[mt][nt][3]};
            if (scatter) {
                int colb = n0 + wn*32 + nt*8;      // section & head uniform per fragment
                int sec = colb / C_N;
                int hh = (colb % C_N) >> 6;
                int dd = (colb & 63) + ra*2;
                float* base = (sec == 0) ? g_q : (sec == 1) ? g_k : (sec == 2) ? g_v : g_g;
                *(float2*)(base + ((size_t)(hh*T_N + row)*D_N + dd)) = c0;
                *(float2*)(base + ((size_t)(hh*T_N + row + 8)*D_N + dd)) = c1;
            } else {
                int col = n0 + wn*32 + nt*8 + ra*2;
                *(float2*)(C + (size_t)row*N + col) = c0;
                *(float2*)(C + (size_t)(row+8)*N + col) = c1;
            }
        }
    }
}

// ---------------- tf32 GEMM 64x128 (for out projection) ----------------
#define STG64 ((64+128)*GS)

__global__ __launch_bounds__(256, 2) void gemm_tf32_64(const float* __restrict__ A,
        const float* __restrict__ B, float* __restrict__ C, int M, int N, int K) {
    extern __shared__ unsigned gsm[];
    int tid = threadIdx.x;
    int lane = tid & 31, w = tid >> 5;
    int wm = w >> 2, wn = w & 3;
    int m0 = blockIdx.y*64, n0 = blockIdx.x*128;
    int lr = tid >> 3, lc = (tid & 7)*4;
    const float* Ap = A + (size_t)(m0+lr)*K + lc;
    const float* Bp = B + (size_t)(n0+lr)*K + lc;

    float acc[2][4][4];
    #pragma unroll
    for (int i = 0; i < 2; ++i)
        #pragma unroll
        for (int j = 0; j < 4; ++j)
            #pragma unroll
            for (int v = 0; v < 4; ++v) acc[i][j][v] = 0.f;

    int qa = lane >> 2, ra = lane & 3;

    float4 pra[2], prb[4];
    #pragma unroll
    for (int p = 0; p < 2; ++p) pra[p] = *(const float4*)(Ap + (size_t)p*32*K);
    #pragma unroll
    for (int p = 0; p < 4; ++p) prb[p] = *(const float4*)(Bp + (size_t)p*32*K);
    {
        unsigned* As = gsm;
        unsigned* Bs = gsm + 64*GS;
        #pragma unroll
        for (int p = 0; p < 2; ++p) {
            unsigned* as = As + (lr + p*32)*GS + lc;
            as[0]=f2tf32(pra[p].x); as[1]=f2tf32(pra[p].y); as[2]=f2tf32(pra[p].z); as[3]=f2tf32(pra[p].w);
        }
        #pragma unroll
        for (int p = 0; p < 4; ++p) {
            unsigned* bs = Bs + (lr + p*32)*GS + lc;
            bs[0]=f2tf32(prb[p].x); bs[1]=f2tf32(prb[p].y); bs[2]=f2tf32(prb[p].z); bs[3]=f2tf32(prb[p].w);
        }
    }
    __syncthreads();
    int cur = 0;

    for (int kb = 0; kb < K; kb += 32) {
        bool nxt = (kb + 32 < K);
        if (nxt) {
            #pragma unroll
            for (int p = 0; p < 2; ++p) pra[p] = *(const float4*)(Ap + (size_t)p*32*K + kb + 32);
            #pragma unroll
            for (int p = 0; p < 4; ++p) prb[p] = *(const float4*)(Bp + (size_t)p*32*K + kb + 32);
        }
        unsigned* As = gsm + cur*STG64;
        unsigned* Bs = As + 64*GS;
        #pragma unroll
        for (int ks = 0; ks < 4; ++ks) {
            unsigned af[2][4], bf[4][2];
            #pragma unroll
            for (int mt = 0; mt < 2; ++mt) {
                const unsigned* p = As + (wm*32 + mt*16 + qa)*GS + ks*8 + ra;
                af[mt][0] = p[0];
                af[mt][1] = p[8*GS];
                af[mt][2] = p[4];
                af[mt][3] = p[8*GS + 4];
            }
            #pragma unroll
            for (int nt = 0; nt < 4; ++nt) {
                const unsigned* p = Bs + (wn*32 + nt*8 + qa)*GS + ks*8 + ra;
                bf[nt][0] = p[0];
                bf[nt][1] = p[4];
            }
            #pragma unroll
            for (int mt = 0; mt < 2; ++mt)
                #pragma unroll
                for (int nt = 0; nt < 4; ++nt)
                    mma_tf32(acc[mt][nt], af[mt], bf[nt]);
        }
        if (nxt) {
            unsigned* As2 = gsm + (cur^1)*STG64;
            unsigned* Bs2 = As2 + 64*GS;
            #pragma unroll
            for (int p = 0; p < 2; ++p) {
                unsigned* as = As2 + (lr + p*32)*GS + lc;
                as[0]=f2tf32(pra[p].x); as[1]=f2tf32(pra[p].y); as[2]=f2tf32(pra[p].z); as[3]=f2tf32(pra[p].w);
            }
            #pragma unroll
            for (int p = 0; p < 4; ++p) {
                unsigned* bs = Bs2 + (lr + p*32)*GS + lc;
                bs[0]=f2tf32(prb[p].x); bs[1]=f2tf32(prb[p].y); bs[2]=f2tf32(prb[p].z); bs[3]=f2tf32(prb[p].w);
            }
            __syncthreads();
            cur ^= 1;
        }
    }

    #pragma unroll
    for (int mt = 0; mt < 2; ++mt) {
        int row = m0 + wm*32 + mt*16 + qa;
        #pragma unroll
        for (int nt = 0; nt < 4; ++nt) {
            int col = n0 + wn*32 + nt*8 + ra*2;
            float2 c0 = {acc[mt][nt][0], acc[mt][nt][1]};
            float2 c1 = {acc[mt][nt][2], acc[mt][nt][3]};
            *(float2*)(C + (size_t)row*N + col) = c0;
            *(float2*)(C + (size_t)(row+8)*N + col) = c1;
        }
    }
}

// ---------------- rmsnorm g in place (quantize to tf32) + g2 ----------------
__global__ __launch_bounds__(256) void rmsnorm_g(const float* __restrict__ gnw) {
    int gw = (blockIdx.x*256 + threadIdx.x) >> 5;
    int lane = threadIdx.x & 31;
    if (gw >= H_N*T_N) return;
    float* p = g_g + (size_t)gw*D_N + lane*2;
    float2 gv = *(float2*)p;
    float ss = gv.x*gv.x + gv.y*gv.y;
    #pragma unroll
    for (int m = 16; m; m >>= 1) ss += __shfl_xor_sync(0xffffffffu, ss, m);
    float r = rsqrtf(ss*(1.0f/D_N) + 1e-6f);
    float2 wv = *(const float2*)(gnw + lane*2);
    float q0 = __uint_as_float(f2tf32(gv.x*r*wv.x));
    float q1 = __uint_as_float(f2tf32(gv.y*r*wv.y));
    float2 gq = {q0, q1};
    *(float2*)p = gq;
    float s2 = q0*q0 + q1*q1;
    #pragma unroll
    for (int m = 16; m; m >>= 1) s2 += __shfl_xor_sync(0xffffffffu, s2, m);
    if (lane == 0) g_g2[gw] = s2;
}

// ---------------- split-j flash attention partial (tensor-core, warp-decoupled) ----------------
#define QS_O   0
#define GI_O   4352
#define KS_O   8704
#define GJ_O   13056
#define VS_O   17408
#define PS_O   21760
#define G2I_O  26368
#define G2J_O  26432
#define DWS_O  26496
#define MA_O   26560
#define MB_O   26624
#define LA_O   26688
#define LB_O   26752
#define ATT_SMEM_WORDS 26816
#define ATT_SMEM_BYTES (ATT_SMEM_WORDS*4)

__global__ __launch_bounds__(256, 2) void attn_part() {
    extern __shared__ unsigned smu[];
    float* smf = (float*)smu;
    unsigned* Qs  = smu + QS_O;          // [64][68] tf32
    unsigned* Gis = smu + GI_O;          // [64][68] tf32 (pre-quantized g)
    unsigned* Ks  = smu + KS_O;          // also merge bufA (wn=0)
    unsigned* Gjs = smu + GJ_O;          // also merge bufB (wn=1)
    unsigned* Vs  = smu + VS_O;          // [d][j] tf32 (transposed)
    float* g2i_s = smf + G2I_O;
    float* g2j_s = smf + G2J_O;
    float* dws   = smf + DWS_O;
    float* mA = smf + MA_O; float* mB = smf + MB_O;
    float* lA = smf + LA_O; float* lB = smf + LB_O;

    int bid = blockIdx.x;
    int h = bid % H_N;
    int u = bid / H_N;
    int it = c_uit[u], cch = c_uc[u];
    int i0 = it * 64;
    int jt0 = cch*4, jt1 = min(jt0+3, it);
    int uidx = c_off[it] + cch;
    int tid = threadIdx.x;
    int lane = tid & 31, w = tid >> 5;
    int wm = w >> 1, wn = w & 1;
    int qa = lane >> 2, ra = lane & 3;
    int q2 = qa & 3;
    int row0 = wm*16 + qa;
    unsigned* Psw = smu + PS_O + w*576;   // warp-local P: [16][36]

    int fast = g_c.fastf[h];
    float i4t0 = g_c.i4t0[h], fA = g_c.fA[h], fB = g_c.fB[h];
    float neghb = g_c.neghb[h], dpl = g_c.dpl[h], glk = g_c.glk[h];

    const float* qg  = g_q + (size_t)(h*T_N + i0)*D_N;
    const float* gig = g_g + (size_t)(h*T_N + i0)*D_N;
    #pragma unroll
    for (int p = 0; p < 4; ++p) {
        int e = tid + p*256;
        int r = e >> 4, dc = (e & 15)*4;
        float4 a = *(const float4*)(qg + r*D_N + dc);
        uint4 ua; ua.x=f2tf32(a.x); ua.y=f2tf32(a.y); ua.z=f2tf32(a.z); ua.w=f2tf32(a.w);
        *(uint4*)(Qs + r*68 + dc) = ua;
        float4 b = *(const float4*)(gig + r*D_N + dc);
        uint4 ub; ub.x=__float_as_uint(b.x); ub.y=__float_as_uint(b.y);
        ub.z=__float_as_uint(b.z); ub.w=__float_as_uint(b.w);   // already tf32-quantized
        *(uint4*)(Gis + r*68 + dc) = ub;
    }
    if (tid < 64) g2i_s[tid] = g_g2[h*T_N + i0 + tid];

    float m_r[2] = {-1e30f, -1e30f}, l_r[2] = {0.f, 0.f};
    float apv[8][4];
    #pragma unroll
    for (int nt = 0; nt < 8; ++nt)
        #pragma unroll
        for (int c = 0; c < 4; ++c) apv[nt][c] = 0.f;

    for (int jt = jt0; jt <= jt1; ++jt) {
        int j0 = jt*64;
        __syncthreads();   // PV of previous tile done before overwrite
        const float* kg  = g_k + (size_t)(h*T_N + j0)*D_N;
        const float* gjg = g_g + (size_t)(h*T_N + j0)*D_N;
        const float* vg  = g_v + (size_t)(h*T_N + j0)*D_N;
        #pragma unroll
        for (int p = 0; p < 4; ++p) {
            int e = tid + p*256;
            int r = e >> 4, dc = (e & 15)*4;
            float4 a = *(const float4*)(kg + r*D_N + dc);
            uint4 ua; ua.x=f2tf32(a.x); ua.y=f2tf32(a.y); ua.z=f2tf32(a.z); ua.w=f2tf32(a.w);
            *(uint4*)(Ks + r*68 + dc) = ua;
            float4 b = *(const float4*)(gjg + r*D_N + dc);
            uint4 ub; ub.x=__float_as_uint(b.x); ub.y=__float_as_uint(b.y);
            ub.z=__float_as_uint(b.z); ub.w=__float_as_uint(b.w);
            *(uint4*)(Gjs + r*68 + dc) = ub;
            int j = e & 63, dg = (e >> 6)*4;
            float4 v = *(const float4*)(vg + j*D_N + dg);
            Vs[(dg+0)*68 + j] = f2tf32(v.x);
            Vs[(dg+1)*68 + j] = f2tf32(v.y);
            Vs[(dg+2)*68 + j] = f2tf32(v.z);
            Vs[(dg+3)*68 + j] = f2tf32(v.w);
        }
        if (tid < 64) g2j_s[tid] = g_g2[h*T_N + j0 + tid];
        __syncthreads();

        // ---- QK + GG MMAs ----
        float dqk[4][4], dgg[4][4];
        #pragma unroll
        for (int nt = 0; nt < 4; ++nt)
            #pragma unroll
            for (int c = 0; c < 4; ++c) { dqk[nt][c] = 0.f; dgg[nt][c] = 0.f; }

        #pragma unroll
        for (int ks = 0; ks < 8; ++ks) {
            int kc = ks*8 + ra;
            const unsigned* qp = Qs + row0*68 + kc;
            unsigned af[4] = {qp[0], qp[8*68], qp[4], qp[8*68+4]};
            const unsigned* gp = Gis + row0*68 + kc;
            unsigned gf[4] = {gp[0], gp[8*68], gp[4], gp[8*68+4]};
            #pragma unroll
            for (int nt = 0; nt < 4; ++nt) {
                int nb = wn*32 + nt*8 + qa;
                const unsigned* kp = Ks + nb*68 + kc;
                unsigned bf[2] = {kp[0], kp[4]};
                const unsigned* gjp = Gjs + nb*68 + kc;
                unsigned bgf[2] = {gjp[0], gjp[4]};
                mma_tf32(dqk[nt], af, bf);
                mma_tf32(dgg[nt], gf, bgf);
            }
        }

        // ---- epilogue: blended scores (warp-local over own 32-col half) ----
        int diag = (jt == it);
        float mt[2] = {-1e30f, -1e30f};
        #pragma unroll
        for (int nt = 0; nt < 4; ++nt) {
            #pragma unroll
            for (int c = 0; c < 4; ++c) {
                int rh = c >> 1, pp = c & 1;
                int rl = row0 + rh*8;
                int cl = wn*32 + nt*8 + 2*ra + pp;
                float bl = -1e30f;
                if (j0 + cl <= i0 + rl) {
                    float s = fmaxf(g2i_s[rl] + g2j_s[cl] - 2.f*dgg[nt][c], 0.f);
                    if (fast) {
                        bl = fmaf(dqk[nt][c], dpl, fmaf(fA, lg2f_(fmaf(s, i4t0, 1.f)), fB));
                    } else {
                        float Ksum = 0.f;
                        #pragma unroll
                        for (int t = 0; t < 8; ++t) {
                            float uu = fmaf(s, g_c.inv4tau[h][t], 1.f);
                            Ksum = fmaf(g_c.wte[h][t], ex2f_(neghb * lg2f_(uu)), Ksum);
                        }
                        bl = fmaf(dqk[nt][c], dpl, glk * lg2f_(Ksum));
                    }
                }
                dqk[nt][c] = bl;
                mt[rh] = fmaxf(mt[rh], bl);
            }
        }
        mt[0] = fmaxf(mt[0], __shfl_xor_sync(0xffffffffu, mt[0], 1));
        mt[0] = fmaxf(mt[0], __shfl_xor_sync(0xffffffffu, mt[0], 2));
        mt[1] = fmaxf(mt[1], __shfl_xor_sync(0xffffffffu, mt[1], 1));
        mt[1] = fmaxf(mt[1], __shfl_xor_sync(0xffffffffu, mt[1], 2));
        float sc[2], mcl[2];
        #pragma unroll
        for (int rh = 0; rh < 2; ++rh) {
            float mnew = fmaxf(m_r[rh], mt[rh]);
            sc[rh] = ex2f_((m_r[rh] - mnew)*LOG2E);
            m_r[rh] = mnew;
            mcl[rh] = fmaxf(mnew, -1e20f);   // clamp: empty half -> p=0 not 1
        }
        #pragma unroll
        for (int nt = 0; nt < 8; ++nt) {
            apv[nt][0] *= sc[0]; apv[nt][1] *= sc[0];
            apv[nt][2] *= sc[1]; apv[nt][3] *= sc[1];
        }
        float psum[2] = {0.f, 0.f};
        #pragma unroll
        for (int nt = 0; nt < 4; ++nt) {
            int cl = wn*32 + nt*8 + 2*ra;
            float p00 = ex2f_((dqk[nt][0] - mcl[0])*LOG2E);
            float p01 = ex2f_((dqk[nt][1] - mcl[0])*LOG2E);
            float p10 = ex2f_((dqk[nt][2] - mcl[1])*LOG2E);
            float p11 = ex2f_((dqk[nt][3] - mcl[1])*LOG2E);
            psum[0] += p00 + p01;
            psum[1] += p10 + p11;
            if (diag) {
                int rl0 = row0, rl1 = row0 + 8;
                if (rl0 == cl) dws[rl0] = p00; else if (rl0 == cl+1) dws[rl0] = p01;
                if (rl1 == cl) dws[rl1] = p10; else if (rl1 == cl+1) dws[rl1] = p11;
            }
            // warp-local P store, xor-swizzled
            int colp = ((nt ^ q2)*8) + 2*ra;
            uint2 s0; s0.x = f2tf32(p00); s0.y = f2tf32(p01);
            uint2 s1; s1.x = f2tf32(p10); s1.y = f2tf32(p11);
            *(uint2*)(Psw + qa*36 + colp) = s0;
            *(uint2*)(Psw + (qa+8)*36 + colp) = s1;
        }
        psum[0] += __shfl_xor_sync(0xffffffffu, psum[0], 1);
        psum[0] += __shfl_xor_sync(0xffffffffu, psum[0], 2);
        psum[1] += __shfl_xor_sync(0xffffffffu, psum[1], 1);
        psum[1] += __shfl_xor_sync(0xffffffffu, psum[1], 2);
        l_r[0] = l_r[0]*sc[0] + psum[0];
        l_r[1] = l_r[1]*sc[1] + psum[1];
        __syncwarp();

        // ---- PV MMAs (k=32 over own j-half, full 64-d output) ----
        #pragma unroll
        for (int ks = 0; ks < 4; ++ks) {
            const unsigned* pp_ = Psw + qa*36 + ((ks ^ q2)*8) + ra;
            unsigned pf[4] = {pp_[0], pp_[8*36], pp_[4], pp_[8*36+4]};
            int jc = wn*32 + ks*8 + ra;
            #pragma unroll
            for (int nt = 0; nt < 8; ++nt) {
                const unsigned* vp = Vs + (nt*8 + qa)*68 + jc;
                unsigned vf[2] = {vp[0], vp[4]};
                mma_tf32(apv[nt], pf, vf);
            }
        }
    }

    // ---- wn-pair merge + write partials ----
    __syncthreads();   // Ks/Gjs free for reuse; dws visible
    {
        float* buf = (wn == 0) ? (float*)Ks : (float*)Gjs;
        #pragma unroll
        for (int nt = 0; nt < 8; ++nt) {
            float2 a0 = {apv[nt][0], apv[nt][1]};
            float2 a1 = {apv[nt][2], apv[nt][3]};
            *(float2*)(buf + row0*68 + nt*8 + 2*ra) = a0;
            *(float2*)(buf + (row0+8)*68 + nt*8 + 2*ra) = a1;
        }
        if (ra == 0) {
            float* mArr = wn ? mB : mA; float* lArr = wn ? lB : lA;
            mArr[row0] = m_r[0]; mArr[row0+8] = m_r[1];
            lArr[row0] = l_r[0]; lArr[row0+8] = l_r[1];
        }
    }
    __syncthreads();
    {
        int r = tid >> 2, c0 = (tid & 3)*16;
        float m0v = mA[r], m1v = mB[r];
        float mf = fmaxf(m0v, m1v);
        float e0 = ex2f_((m0v - mf)*LOG2E);
        float e1 = ex2f_((m1v - mf)*LOG2E);
        int base = (h*40 + uidx)*64;
        if ((tid & 3) == 0) {
            g_pm[base + r] = mf;
            g_pl[base + r] = lA[r]*e0 + lB[r]*e1;
            if (jt1 == it) {
                float mo = (r >= 32) ? m1v : m0v;
                g_dw[(h*16 + it)*64 + r] = dws[r] * ex2f_((mo - mf)*LOG2E);
            }
        }
        const float* bAp = (const float*)Ks + r*68 + c0;
        const float* bBp = (const float*)Gjs + r*68 + c0;
        #pragma unroll
        for (int cc = 0; cc < 16; cc += 4) {
            float4 a = *(const float4*)(bAp + cc);
            float4 b = *(const float4*)(bBp + cc);
            float4 o;
            o.x = a.x*e0 + b.x*e1;
            o.y = a.y*e0 + b.y*e1;
            o.z = a.z*e0 + b.z*e1;
            o.w = a.w*e0 + b.w*e1;
            *(float4*)(g_pacc + (size_t)(base + r)*64 + c0 + cc) = o;
        }
    }
}

// ---------------- combine partials -> g_y ----------------
__global__ __launch_bounds__(256) void attn_combine() {
    int bid = blockIdx.x;
    int h = bid % H_N, it = bid / H_N;
    int i0 = it * 64;
    int nc = it/4 + 1;
    int tid = threadIdx.x;
    int row = tid >> 2;
    int c0 = (tid & 3) * 16;
    int b0 = (h*40 + c_off[it])*64 + row;

    float mv[4], sc4[4];
    float gm = -1e30f;
    for (int c = 0; c < nc; ++c) { mv[c] = g_pm[b0 + c*64]; gm = fmaxf(gm, mv[c]); }
    float L = 0.f;
    for (int c = 0; c < nc; ++c) {
        sc4[c] = ex2f_((mv[c]-gm)*LOG2E);
        L += g_pl[b0 + c*64] * sc4[c];
    }
    float linv = 1.f / fmaxf(L, 1e-12f);
    float pii = g_dw[(h*16 + it)*64 + row] * sc4[nc-1] * linv;
    float alpha = g_c.alpha;
    float ca = 1.f - alpha;
    float cb = alpha / (1.f + pii);
    float outs = g_c.outs[h];

    for (int cc = 0; cc < 16; cc += 4) {
        float ax=0.f, ay=0.f, az=0.f, aw=0.f;
        for (int c = 0; c < nc; ++c) {
            float4 p = *(const float4*)(g_pacc + (size_t)(b0 + c*64)*64 + c0 + cc);
            float s = sc4[c];
            ax = fmaf(p.x, s, ax); ay = fmaf(p.y, s, ay);
            az = fmaf(p.z, s, az); aw = fmaf(p.w, s, aw);
        }
        float4 v = *(const float4*)(g_v + (size_t)(h*T_N + i0 + row)*D_N + c0 + cc);
        float4 o;
        float p0 = ax*linv, p1 = ay*linv, p2 = az*linv, p3 = aw*linv;
        o.x = outs * (ca*p0 + cb*(p0 + pii*v.x));
        o.y = outs * (ca*p1 + cb*(p1 + pii*v.y));
        o.z = outs * (ca*p2 + cb*(p2 + pii*v.z));
        o.w = outs * (ca*p3 + cb*(p3 + pii*v.w));
        *(float4*)(g_y + (size_t)(i0 + row)*C_N + h*D_N + c0 + cc) = o;
    }
}

// ---------------- launch ----------------
extern "C" void kernel_launch(void* const* d_in, const int* in_sizes, int n_in,
                              void* d_out, int out_size) {
    const float* x         = (const float*)d_in[0];
    const float* W_qkvg    = (const float*)d_in[1];
    const float* W_out     = (const float*)d_in[2];
    const float* lam       = (const float*)d_in[3];
    const float* log_tau   = (const float*)d_in[4];
    const float* logit_w   = (const float*)d_in[5];
    const float* beta      = (const float*)d_in[6];
    const float* out_scale = (const float*)d_in[7];
    const float* dp_scale  = (const float*)d_in[8];
    const float* logk_sc   = (const float*)d_in[9];
    const float* dt_logit  = (const float*)d_in[10];
    const float* gnw       = (const float*)d_in[11];
    float* out = (float*)d_out;

    float* y_p = nullptr;
    cudaGetSymbolAddress((void**)&y_p, g_y);

    const int G128_SMEM = 2*STG128*4;
    const int G64_SMEM  = 2*STG64*4;
    cudaFuncSetAttribute(gemm_tf32_128, cudaFuncAttributeMaxDynamicSharedMemorySize, G128_SMEM);
    cudaFuncSetAttribute(gemm_tf32_64,  cudaFuncAttributeMaxDynamicSharedMemorySize, G64_SMEM);
    cudaFuncSetAttribute(attn_part, cudaFuncAttributeMaxDynamicSharedMemorySize, ATT_SMEM_BYTES);

    const_kernel<<<1, 32>>>(lam, log_tau, logit_w, beta, out_scale, dp_scale, logk_sc, dt_logit);
    gemm_tf32_128<<<dim3(3072/128, 1024/128), 256, G128_SMEM>>>(x, W_qkvg, nullptr, T_N, 4*C_N, C_N, 1);
    rmsnorm_g<<<(H_N*T_N*32)/256, 256>>>(gnw);
    attn_part<<<480, 256, ATT_SMEM_BYTES>>>();
    attn_combine<<<192, 256>>>();
    gemm_tf32_64<<<dim3(768/128, 1024/64), 256, G64_SMEM>>>(y_p, W_out, out, T_N, C_N, C_N);
}

// round 7
// speedup vs baseline: 1.3744x; 1.3744x over previous
#include <cuda_runtime.h>
#include <cuda_bf16.h>

#define T_N 1024
#define C_N 768
#define H_N 12
#define D_N 64
#define NT_N 8
#define LOG2E 1.4426950408889634f

// ---------------- scratch (static device globals; no allocation) ----------------
__device__ float g_q[H_N * T_N * D_N];       // [H][T][D]
__device__ float g_k[H_N * T_N * D_N];
__device__ float g_v[H_N * T_N * D_N];
__device__ float g_g[H_N * T_N * D_N];       // raw then rmsnormed+tf32-quantized g
__device__ float g_g2[H_N * T_N];            // ||ghat||^2 per (h,t)
__device__ float g_y[T_N * C_N];             // attention out, [T][C] layout
__device__ float g_M[H_N];                   // per-head safe score max (log2 domain)

// split-j partials: 40 units per head (chunks of <=4 j-tiles), all at scale 2^-M
__device__ float g_pacc[H_N * 40 * 64 * 64]; // [h][unit][row][col]
__device__ float g_pl[H_N * 40 * 64];
__device__ float g_dw[H_N * 16 * 64];        // diag weights per (h,it,row)

// unit tables: heavy (4-tile) units first for scheduling
__constant__ int c_uit[40] = {15,15,15,15,14,14,14,13,13,13,12,12,12,11,11,11,10,10,9,9,8,8,7,7,6,5,4,3,
                              14,10,6,2, 13,9,5,1, 12,8,4,0};
__constant__ int c_uc[40]  = { 0, 1, 2, 3, 0, 1, 2, 0, 1, 2, 0, 1, 2, 0, 1, 2, 0, 1,0,1,0,1,0,1,0,0,0,0,
                               3, 2,1,0,  3,2,1,0,  3,2,1,0};
__constant__ int c_off[16] = {0,1,2,3,4,6,8,10,12,15,18,21,24,28,32,36};

struct Consts {
    float inv4tau[H_N][NT_N];
    float wte[H_N][NT_N];
    float neghb[H_N];
    float dpl[H_N];           // lam * dp_scale/(8*0.8)
    float glk[H_N];           // (1-lam) * logk_scale * ln2
    float outs[H_N];
    float fA[H_N], fB[H_N], i4t0[H_N];
    int   fastf[H_N];
    float alpha;
};
__device__ Consts g_c;

__device__ __forceinline__ float ex2f_(float x){ float y; asm("ex2.approx.ftz.f32 %0, %1;":"=f"(y):"f"(x)); return y; }
__device__ __forceinline__ float lg2f_(float x){ float y; asm("lg2.approx.ftz.f32 %0, %1;":"=f"(y):"f"(x)); return y; }
__device__ __forceinline__ unsigned f2tf32(float x){ unsigned y; asm("cvt.rna.tf32.f32 %0, %1;":"=r"(y):"f"(x)); return y; }

__device__ __forceinline__ void mma_tf32(float* d, const unsigned* a, const unsigned* b) {
    asm volatile(
      "mma.sync.aligned.m16n8k8.row.col.f32.tf32.tf32.f32 "
      "{%0,%1,%2,%3}, {%4,%5,%6,%7}, {%8,%9}, {%0,%1,%2,%3};\n"
      : "+f"(d[0]), "+f"(d[1]), "+f"(d[2]), "+f"(d[3])
      : "r"(a[0]), "r"(a[1]), "r"(a[2]), "r"(a[3]), "r"(b[0]), "r"(b[1]));
}

// ---------------- constants precompute ----------------
__global__ void const_kernel(const float* lam_p, const float* log_tau,
                             const float* logit_w, const float* beta,
                             const float* out_scale, const float* dp_scale,
                             const float* logk_scale, const float* dt_logit) {
    if (threadIdx.x != 0 || blockIdx.x != 0) return;
    float lam = lam_p[0];
    for (int h = 0; h < H_N; ++h) {
        float mx = -1e30f;
        for (int t = 0; t < NT_N; ++t) mx = fmaxf(mx, logit_w[h*NT_N+t]);
        float s = 0.f, e[NT_N];
        for (int t = 0; t < NT_N; ++t) { e[t] = expf(logit_w[h*NT_N+t]-mx); s += e[t]; }
        float W = 0.f;
        for (int t = 0; t < NT_N; ++t) { g_c.wte[h][t] = e[t]/s + 1e-12f; W += g_c.wte[h][t]; }
        for (int t = 0; t < NT_N; ++t) {
            float tau = fmaxf(expf(log_tau[h*NT_N+t]), 1e-6f);
            g_c.inv4tau[h][t] = 1.f/(4.f*tau);
        }
        float bc = fminf(fmaxf(beta[h], 0.5f), 2.5f);
        float neghb = -0.5f*bc;
        float dpc = dp_scale[h]/(8.0f*0.8f);
        float lks = logk_scale[h]*0.6931471805599453f;
        g_c.neghb[h] = neghb;
        g_c.dpl[h]   = lam*dpc;
        g_c.glk[h]   = (1.f-lam)*lks;
        g_c.outs[h]  = out_scale[h];
        int same = 1;
        for (int t = 1; t < NT_N; ++t) if (g_c.inv4tau[h][t] != g_c.inv4tau[h][0]) same = 0;
        g_c.fastf[h] = same;
        g_c.i4t0[h]  = g_c.inv4tau[h][0];
        g_c.fA[h]    = g_c.glk[h]*neghb;
        g_c.fB[h]    = g_c.glk[h]*log2f(W);
    }
    g_c.alpha = 0.1f/(1.f+expf(-dt_logit[0]));
}

// ---------------- per-head safe max bound (log2 score domain) ----------------
__global__ __launch_bounds__(256) void bound_kernel() {
    __shared__ float red[3*256];
    int h = blockIdx.x, tid = threadIdx.x;
    float mq = 0.f, mk = 0.f, mg = 0.f;
    const float* qb = g_q + (size_t)h*T_N*D_N;
    const float* kb = g_k + (size_t)h*T_N*D_N;
    for (int t = tid; t < T_N; t += 256) {
        float sq = 0.f, sk = 0.f;
        const float4* qr = (const float4*)(qb + (size_t)t*D_N);
        const float4* kr = (const float4*)(kb + (size_t)t*D_N);
        #pragma unroll
        for (int i = 0; i < 16; ++i) {
            float4 a = qr[i], b = kr[i];
            sq += a.x*a.x + a.y*a.y + a.z*a.z + a.w*a.w;
            sk += b.x*b.x + b.y*b.y + b.z*b.z + b.w*b.w;
        }
        mq = fmaxf(mq, sq); mk = fmaxf(mk, sk);
        mg = fmaxf(mg, g_g2[h*T_N + t]);
    }
    red[tid] = mq; red[256+tid] = mk; red[512+tid] = mg;
    __syncthreads();
    for (int st = 128; st; st >>= 1) {
        if (tid < st) {
            red[tid]     = fmaxf(red[tid],     red[tid+st]);
            red[256+tid] = fmaxf(red[256+tid], red[256+tid+st]);
            red[512+tid] = fmaxf(red[512+tid], red[512+tid+st]);
        }
        __syncthreads();
    }
    if (tid == 0) {
        mq = red[0]; mk = red[256]; mg = red[512];
        float dplL = g_c.dpl[h]*LOG2E;
        float bqk = fabsf(dplL)*sqrtf(mq*mk);
        float smax = 4.f*mg + 1.f;
        float kmax;
        if (g_c.fastf[h]) {
            float a = g_c.fA[h]*LOG2E, b = g_c.fB[h]*LOG2E;
            float t1 = fmaf(a, log2f(fmaf(smax, g_c.i4t0[h], 1.f)), b);
            kmax = fmaxf(t1, b);
        } else {
            float glkL = g_c.glk[h]*LOG2E;
            float W = 0.f, Kmin = 0.f;
            for (int t = 0; t < NT_N; ++t) {
                W += g_c.wte[h][t];
                Kmin += g_c.wte[h][t]*powf(fmaf(smax, g_c.inv4tau[h][t], 1.f), g_c.neghb[h]);
            }
            kmax = fmaxf(glkL*log2f(W), glkL*log2f(Kmin));
        }
        g_M[h] = bqk + kmax + 1.f;
    }
}

// ---------------- tf32 GEMM 128x128, double-buffered; optional qkvg scatter ----------------
#define GS 36
#define STG128 (2*128*GS)   // words per stage (A tile + B tile)

__global__ __launch_bounds__(256, 2) void gemm_tf32_128(const float* __restrict__ A,
        const float* __restrict__ B, float* __restrict__ C, int M, int N, int K, int scatter) {
    extern __shared__ unsigned gsm[];
    int tid = threadIdx.x;
    int lane = tid & 31, w = tid >> 5;
    int wm = w >> 2, wn = w & 3;
    int m0 = blockIdx.y*128, n0 = blockIdx.x*128;
    int lr = tid >> 3, lc = (tid & 7)*4;
    const float* Ap = A + (size_t)(m0+lr)*K + lc;
    const float* Bp = B + (size_t)(n0+lr)*K + lc;

    float acc[4][4][4];
    #pragma unroll
    for (int i = 0; i < 4; ++i)
        #pragma unroll
        for (int j = 0; j < 4; ++j)
            #pragma unroll
            for (int v = 0; v < 4; ++v) acc[i][j][v] = 0.f;

    int qa = lane >> 2, ra = lane & 3;

    float4 pra[4], prb[4];
    #pragma unroll
    for (int p = 0; p < 4; ++p) {
        pra[p] = *(const float4*)(Ap + (size_t)p*32*K);
        prb[p] = *(const float4*)(Bp + (size_t)p*32*K);
    }
    {   // store stage 0
        unsigned* As = gsm;
        unsigned* Bs = gsm + 128*GS;
        #pragma unroll
        for (int p = 0; p < 4; ++p) {
            unsigned* as = As + (lr + p*32)*GS + lc;
            unsigned* bs = Bs + (lr + p*32)*GS + lc;
            as[0]=f2tf32(pra[p].x); as[1]=f2tf32(pra[p].y); as[2]=f2tf32(pra[p].z); as[3]=f2tf32(pra[p].w);
            bs[0]=f2tf32(prb[p].x); bs[1]=f2tf32(prb[p].y); bs[2]=f2tf32(prb[p].z); bs[3]=f2tf32(prb[p].w);
        }
    }
    __syncthreads();
    int cur = 0;

    for (int kb = 0; kb < K; kb += 32) {
        bool nxt = (kb + 32 < K);
        if (nxt) {
            #pragma unroll
            for (int p = 0; p < 4; ++p) {
                pra[p] = *(const float4*)(Ap + (size_t)p*32*K + kb + 32);
                prb[p] = *(const float4*)(Bp + (size_t)p*32*K + kb + 32);
            }
        }
        unsigned* As = gsm + cur*STG128;
        unsigned* Bs = As + 128*GS;
        #pragma unroll
        for (int ks = 0; ks < 4; ++ks) {
            unsigned af[4][4], bf[4][2];
            #pragma unroll
            for (int mt = 0; mt < 4; ++mt) {
                const unsigned* p = As + (wm*64 + mt*16 + qa)*GS + ks*8 + ra;
                af[mt][0] = p[0];
                af[mt][1] = p[8*GS];
                af[mt][2] = p[4];
                af[mt][3] = p[8*GS + 4];
            }
            #pragma unroll
            for (int nt = 0; nt < 4; ++nt) {
                const unsigned* p = Bs + (wn*32 + nt*8 + qa)*GS + ks*8 + ra;
                bf[nt][0] = p[0];
                bf[nt][1] = p[4];
            }
            #pragma unroll
            for (int mt = 0; mt < 4; ++mt)
                #pragma unroll
                for (int nt = 0; nt < 4; ++nt)
                    mma_tf32(acc[mt][nt], af[mt], bf[nt]);
        }
        if (nxt) {
            unsigned* As2 = gsm + (cur^1)*STG128;
            unsigned* Bs2 = As2 + 128*GS;
            #pragma unroll
            for (int p = 0; p < 4; ++p) {
                unsigned* as = As2 + (lr + p*32)*GS + lc;
                unsigned* bs = Bs2 + (lr + p*32)*GS + lc;
                as[0]=f2tf32(pra[p].x); as[1]=f2tf32(pra[p].y); as[2]=f2tf32(pra[p].z); as[3]=f2tf32(pra[p].w);
                bs[0]=f2tf32(prb[p].x); bs[1]=f2tf32(prb[p].y); bs[2]=f2tf32(prb[p].z); bs[3]=f2tf32(prb[p].w);
            }
            __syncthreads();
            cur ^= 1;
        }
    }

    #pragma unroll
    for (int mt = 0; mt < 4; ++mt) {
        int row = m0 + wm*64 + mt*16 + qa;
        #pragma unroll
        for (int nt = 0; nt < 4; ++nt) {
            float2 c0 = {acc[mt][nt][0], acc[mt][nt][1]};
            float2 c1 = {acc[mt][nt][2], acc[mt][nt][3]};
            if (scatter) {
                int colb = n0 + wn*32 + nt*8;      // section & head uniform per fragment
                int sec = colb / C_N;
                int hh = (colb % C_N) >> 6;
                int dd = (colb & 63) + ra*2;
                float* base = (sec == 0) ? g_q : (sec == 1) ? g_k : (sec == 2) ? g_v : g_g;
                *(float2*)(base + ((size_t)(hh*T_N + row)*D_N + dd)) = c0;
                *(float2*)(base + ((size_t)(hh*T_N + row + 8)*D_N + dd)) = c1;
            } else {
                int col = n0 + wn*32 + nt*8 + ra*2;
                *(float2*)(C + (size_t)row*N + col) = c0;
                *(float2*)(C + (size_t)(row+8)*N + col) = c1;
            }
        }
    }
}

// ---------------- tf32 GEMM 64x128 (for out projection) ----------------
#define STG64 ((64+128)*GS)

__global__ __launch_bounds__(256, 2) void gemm_tf32_64(const float* __restrict__ A,
        const float* __restrict__ B, float* __restrict__ C, int M, int N, int K) {
    extern __shared__ unsigned gsm[];
    int tid = threadIdx.x;
    int lane = tid & 31, w = tid >> 5;
    int wm = w >> 2, wn = w & 3;
    int m0 = blockIdx.y*64, n0 = blockIdx.x*128;
    int lr = tid >> 3, lc = (tid & 7)*4;
    const float* Ap = A + (size_t)(m0+lr)*K + lc;
    const float* Bp = B + (size_t)(n0+lr)*K + lc;

    float acc[2][4][4];
    #pragma unroll
    for (int i = 0; i < 2; ++i)
        #pragma unroll
        for (int j = 0; j < 4; ++j)
            #pragma unroll
            for (int v = 0; v < 4; ++v) acc[i][j][v] = 0.f;

    int qa = lane >> 2, ra = lane & 3;

    float4 pra[2], prb[4];
    #pragma unroll
    for (int p = 0; p < 2; ++p) pra[p] = *(const float4*)(Ap + (size_t)p*32*K);
    #pragma unroll
    for (int p = 0; p < 4; ++p) prb[p] = *(const float4*)(Bp + (size_t)p*32*K);
    {
        unsigned* As = gsm;
        unsigned* Bs = gsm + 64*GS;
        #pragma unroll
        for (int p = 0; p < 2; ++p) {
            unsigned* as = As + (lr + p*32)*GS + lc;
            as[0]=f2tf32(pra[p].x); as[1]=f2tf32(pra[p].y); as[2]=f2tf32(pra[p].z); as[3]=f2tf32(pra[p].w);
        }
        #pragma unroll
        for (int p = 0; p < 4; ++p) {
            unsigned* bs = Bs + (lr + p*32)*GS + lc;
            bs[0]=f2tf32(prb[p].x); bs[1]=f2tf32(prb[p].y); bs[2]=f2tf32(prb[p].z); bs[3]=f2tf32(prb[p].w);
        }
    }
    __syncthreads();
    int cur = 0;

    for (int kb = 0; kb < K; kb += 32) {
        bool nxt = (kb + 32 < K);
        if (nxt) {
            #pragma unroll
            for (int p = 0; p < 2; ++p) pra[p] = *(const float4*)(Ap + (size_t)p*32*K + kb + 32);
            #pragma unroll
            for (int p = 0; p < 4; ++p) prb[p] = *(const float4*)(Bp + (size_t)p*32*K + kb + 32);
        }
        unsigned* As = gsm + cur*STG64;
        unsigned* Bs = As + 64*GS;
        #pragma unroll
        for (int ks = 0; ks < 4; ++ks) {
            unsigned af[2][4], bf[4][2];
            #pragma unroll
            for (int mt = 0; mt < 2; ++mt) {
                const unsigned* p = As + (wm*32 + mt*16 + qa)*GS + ks*8 + ra;
                af[mt][0] = p[0];
                af[mt][1] = p[8*GS];
                af[mt][2] = p[4];
                af[mt][3] = p[8*GS + 4];
            }
            #pragma unroll
            for (int nt = 0; nt < 4; ++nt) {
                const unsigned* p = Bs + (wn*32 + nt*8 + qa)*GS + ks*8 + ra;
                bf[nt][0] = p[0];
                bf[nt][1] = p[4];
            }
            #pragma unroll
            for (int mt = 0; mt < 2; ++mt)
                #pragma unroll
                for (int nt = 0; nt < 4; ++nt)
                    mma_tf32(acc[mt][nt], af[mt], bf[nt]);
        }
        if (nxt) {
            unsigned* As2 = gsm + (cur^1)*STG64;
            unsigned* Bs2 = As2 + 64*GS;
            #pragma unroll
            for (int p = 0; p < 2; ++p) {
                unsigned* as = As2 + (lr + p*32)*GS + lc;
                as[0]=f2tf32(pra[p].x); as[1]=f2tf32(pra[p].y); as[2]=f2tf32(pra[p].z); as[3]=f2tf32(pra[p].w);
            }
            #pragma unroll
            for (int p = 0; p < 4; ++p) {
                unsigned* bs = Bs2 + (lr + p*32)*GS + lc;
                bs[0]=f2tf32(prb[p].x); bs[1]=f2tf32(prb[p].y); bs[2]=f2tf32(prb[p].z); bs[3]=f2tf32(prb[p].w);
            }
            __syncthreads();
            cur ^= 1;
        }
    }

    #pragma unroll
    for (int mt = 0; mt < 2; ++mt) {
        int row = m0 + wm*32 + mt*16 + qa;
        #pragma unroll
        for (int nt = 0; nt < 4; ++nt) {
            int col = n0 + wn*32 + nt*8 + ra*2;
            float2 c0 = {acc[mt][nt][0], acc[mt][nt][1]};
            float2 c1 = {acc[mt][nt][2], acc[mt][nt][3]};
            *(float2*)(C + (size_t)row*N + col) = c0;
            *(float2*)(C + (size_t)(row+8)*N + col) = c1;
        }
    }
}

// ---------------- rmsnorm g in place (quantize to tf32) + g2 ----------------
__global__ __launch_bounds__(256) void rmsnorm_g(const float* __restrict__ gnw) {
    int gw = (blockIdx.x*256 + threadIdx.x) >> 5;
    int lane = threadIdx.x & 31;
    if (gw >= H_N*T_N) return;
    float* p = g_g + (size_t)gw*D_N + lane*2;
    float2 gv = *(float2*)p;
    float ss = gv.x*gv.x + gv.y*gv.y;
    #pragma unroll
    for (int m = 16; m; m >>= 1) ss += __shfl_xor_sync(0xffffffffu, ss, m);
    float r = rsqrtf(ss*(1.0f/D_N) + 1e-6f);
    float2 wv = *(const float2*)(gnw + lane*2);
    float q0 = __uint_as_float(f2tf32(gv.x*r*wv.x));
    float q1 = __uint_as_float(f2tf32(gv.y*r*wv.y));
    float2 gq = {q0, q1};
    *(float2*)p = gq;
    float s2 = q0*q0 + q1*q1;
    #pragma unroll
    for (int m = 16; m; m >>= 1) s2 += __shfl_xor_sync(0xffffffffu, s2, m);
    if (lane == 0) g_g2[gw] = s2;
}

// ---------------- split-j flash attention partial (fixed-max, no online softmax) ----------------
#define QS_O   0
#define GI_O   4352
#define KS_O   8704
#define GJ_O   13056
#define VS_O   17408            // 72 rows x 68 (row 64 = ones for row-sum, 65-71 zero)
#define PS_O   22304
#define G2I_O  26656
#define G2J_O  26720
#define DWS_O  26784
#define ATT_SMEM_WORDS 26848
#define ATT_SMEM_BYTES (ATT_SMEM_WORDS*4)

__global__ __launch_bounds__(256, 2) void attn_part() {
    extern __shared__ unsigned smu[];
    float* smf = (float*)smu;
    unsigned* Qs  = smu + QS_O;          // [64][68] tf32
    unsigned* Gis = smu + GI_O;          // [64][68] tf32 (pre-quantized g)
    unsigned* Ks  = smu + KS_O;
    unsigned* Gjs = smu + GJ_O;
    unsigned* Vs  = smu + VS_O;          // [72][68]: d rows 0-63, ones row 64
    unsigned* Ps  = smu + PS_O;
    float* g2i_s = smf + G2I_O;
    float* g2j_s = smf + G2J_O;
    float* dws   = smf + DWS_O;

    int bid = blockIdx.x;
    int h = bid % H_N;
    int u = bid / H_N;
    int it = c_uit[u], cch = c_uc[u];
    int i0 = it * 64;
    int jt0 = cch*4, jt1 = min(jt0+3, it);
    int uidx = c_off[it] + cch;
    int tid = threadIdx.x;
    int lane = tid & 31, w = tid >> 5;
    int wm = w >> 1, wn = w & 1;
    int qa = lane >> 2, ra = lane & 3;
    int row0 = wm*16 + qa;

    int fast = g_c.fastf[h];
    float M2   = g_M[h];
    float dplL = g_c.dpl[h]*LOG2E;
    float fAL  = g_c.fA[h]*LOG2E;
    float fBM  = g_c.fB[h]*LOG2E - M2;
    float glkL = g_c.glk[h]*LOG2E;
    float mneg = -M2;
    float i4t0 = g_c.i4t0[h];
    float neghb = g_c.neghb[h];

    const float* qg  = g_q + (size_t)(h*T_N + i0)*D_N;
    const float* gig = g_g + (size_t)(h*T_N + i0)*D_N;
    #pragma unroll
    for (int p = 0; p < 4; ++p) {
        int e = tid + p*256;
        int r = e >> 4, dc = (e & 15)*4;
        float4 a = *(const float4*)(qg + r*D_N + dc);
        uint4 ua; ua.x=f2tf32(a.x); ua.y=f2tf32(a.y); ua.z=f2tf32(a.z); ua.w=f2tf32(a.w);
        *(uint4*)(Qs + r*68 + dc) = ua;
        float4 b = *(const float4*)(gig + r*D_N + dc);
        uint4 ub; ub.x=__float_as_uint(b.x); ub.y=__float_as_uint(b.y);
        ub.z=__float_as_uint(b.z); ub.w=__float_as_uint(b.w);   // already tf32-quantized
        *(uint4*)(Gis + r*68 + dc) = ub;
    }
    if (tid < 64) g2i_s[tid] = g_g2[h*T_N + i0 + tid];
    // ones row (64) + zero rows (65-71) of Vs — written once, never overwritten
    for (int z = tid; z < 8*68; z += 256)
        Vs[64*68 + z] = (z < 64) ? f2tf32(1.f) : 0u;

    float apv[5][4];
    #pragma unroll
    for (int nt = 0; nt < 5; ++nt)
        #pragma unroll
        for (int c = 0; c < 4; ++c) apv[nt][c] = 0.f;

    for (int jt = jt0; jt <= jt1; ++jt) {
        int j0 = jt*64;
        __syncthreads();   // prev tile's Ps/Vs reads done
        const float* kg  = g_k + (size_t)(h*T_N + j0)*D_N;
        const float* gjg = g_g + (size_t)(h*T_N + j0)*D_N;
        const float* vg  = g_v + (size_t)(h*T_N + j0)*D_N;
        #pragma unroll
        for (int p = 0; p < 4; ++p) {
            int e = tid + p*256;
            int r = e >> 4, dc = (e & 15)*4;
            float4 a = *(const float4*)(kg + r*D_N + dc);
            uint4 ua; ua.x=f2tf32(a.x); ua.y=f2tf32(a.y); ua.z=f2tf32(a.z); ua.w=f2tf32(a.w);
            *(uint4*)(Ks + r*68 + dc) = ua;
            float4 b = *(const float4*)(gjg + r*D_N + dc);
            uint4 ub; ub.x=__float_as_uint(b.x); ub.y=__float_as_uint(b.y);
            ub.z=__float_as_uint(b.z); ub.w=__float_as_uint(b.w);
            *(uint4*)(Gjs + r*68 + dc) = ub;
            int j = e & 63, dg = (e >> 6)*4;
            float4 v = *(const float4*)(vg + j*D_N + dg);
            Vs[(dg+0)*68 + j] = f2tf32(v.x);
            Vs[(dg+1)*68 + j] = f2tf32(v.y);
            Vs[(dg+2)*68 + j] = f2tf32(v.z);
            Vs[(dg+3)*68 + j] = f2tf32(v.w);
        }
        if (tid < 64) g2j_s[tid] = g_g2[h*T_N + j0 + tid];
        __syncthreads();

        // ---- QK + GG MMAs ----
        float dqk[4][4], dgg[4][4];
        #pragma unroll
        for (int nt = 0; nt < 4; ++nt)
            #pragma unroll
            for (int c = 0; c < 4; ++c) { dqk[nt][c] = 0.f; dgg[nt][c] = 0.f; }

        #pragma unroll
        for (int ks = 0; ks < 8; ++ks) {
            int kc = ks*8 + ra;
            const unsigned* qp = Qs + row0*68 + kc;
            unsigned af[4] = {qp[0], qp[8*68], qp[4], qp[8*68+4]};
            const unsigned* gp = Gis + row0*68 + kc;
            unsigned gf[4] = {gp[0], gp[8*68], gp[4], gp[8*68+4]};
            #pragma unroll
            for (int nt = 0; nt < 4; ++nt) {
                int nb = wn*32 + nt*8 + qa;
                const unsigned* kp = Ks + nb*68 + kc;
                unsigned bf[2] = {kp[0], kp[4]};
                const unsigned* gjp = Gjs + nb*68 + kc;
                unsigned bgf[2] = {gjp[0], gjp[4]};
                mma_tf32(dqk[nt], af, bf);
                mma_tf32(dgg[nt], gf, bgf);
            }
        }

        // ---- epilogue: p = 2^(score - M), no running max, no row exchange ----
        int diag = (jt == it);
        #pragma unroll
        for (int nt = 0; nt < 4; ++nt) {
            #pragma unroll
            for (int c = 0; c < 4; ++c) {
                int rh = c >> 1, pp = c & 1;
                int rl = row0 + rh*8;
                int cl = wn*32 + nt*8 + 2*ra + pp;
                float p = 0.f;
                if (j0 + cl <= i0 + rl) {
                    float s = fmaxf(g2i_s[rl] + g2j_s[cl] - 2.f*dgg[nt][c], 0.f);
                    float blc;
                    if (fast) {
                        blc = fmaf(dqk[nt][c], dplL, fmaf(fAL, lg2f_(fmaf(s, i4t0, 1.f)), fBM));
                    } else {
                        float Ksum = 0.f;
                        #pragma unroll
                        for (int t = 0; t < 8; ++t) {
                            float uu = fmaf(s, g_c.inv4tau[h][t], 1.f);
                            Ksum = fmaf(g_c.wte[h][t], ex2f_(neghb * lg2f_(uu)), Ksum);
                        }
                        blc = fmaf(dqk[nt][c], dplL, fmaf(glkL, lg2f_(Ksum), mneg));
                    }
                    p = ex2f_(blc);
                }
                dqk[nt][c] = p;
            }
            int cl = wn*32 + nt*8 + 2*ra;
            float p00 = dqk[nt][0], p01 = dqk[nt][1];
            float p10 = dqk[nt][2], p11 = dqk[nt][3];
            if (diag) {
                if (row0 == cl) dws[row0] = p00; else if (row0 == cl+1) dws[row0] = p01;
                if (row0+8 == cl) dws[row0+8] = p10; else if (row0+8 == cl+1) dws[row0+8] = p11;
            }
            uint2 s0; s0.x = f2tf32(p00); s0.y = f2tf32(p01);
            uint2 s1; s1.x = f2tf32(p10); s1.y = f2tf32(p11);
            *(uint2*)(Ps + row0*68 + cl) = s0;
            *(uint2*)(Ps + (row0+8)*68 + cl) = s1;
        }
        __syncthreads();   // Ps visible

        // ---- PV MMAs (k=64; wn==1 adds ones-column for row-sum l) ----
        #pragma unroll
        for (int ks = 0; ks < 8; ++ks) {
            int kc = ks*8 + ra;
            const unsigned* pp_ = Ps + row0*68 + kc;
            unsigned pf[4] = {pp_[0], pp_[8*68], pp_[4], pp_[8*68+4]};
            #pragma unroll
            for (int nt = 0; nt < 5; ++nt) {
                if (nt == 4 && wn == 0) break;
                const unsigned* vp = Vs + (wn*32 + nt*8 + qa)*68 + kc;
                unsigned vf[2] = {vp[0], vp[4]};
                mma_tf32(apv[nt], pf, vf);
            }
        }
    }

    // ---- write partials (all at common scale 2^-M, no merge needed) ----
    int base = (h*40 + uidx)*64;
    #pragma unroll
    for (int nt = 0; nt < 4; ++nt) {
        int cl = wn*32 + nt*8 + 2*ra;
        float2 a0 = {apv[nt][0], apv[nt][1]};
        float2 a1 = {apv[nt][2], apv[nt][3]};
        *(float2*)(g_pacc + (size_t)(base + row0)*64 + cl) = a0;
        *(float2*)(g_pacc + (size_t)(base + row0 + 8)*64 + cl) = a1;
    }
    if (wn == 1 && ra == 0) {
        g_pl[base + row0]     = apv[4][0];
        g_pl[base + row0 + 8] = apv[4][2];
    }
    if (jt1 == it && tid < 64) g_dw[(h*16 + it)*64 + tid] = dws[tid];
}

// ---------------- combine partials -> g_y (same-scale: plain sums) ----------------
__global__ __launch_bounds__(256) void attn_combine() {
    int bid = blockIdx.x;
    int h = bid % H_N, it = bid / H_N;
    int i0 = it * 64;
    int nc = it/4 + 1;
    int tid = threadIdx.x;
    int row = tid >> 2;
    int c0 = (tid & 3) * 16;
    int b0 = (h*40 + c_off[it])*64 + row;

    float L = 0.f;
    for (int c = 0; c < nc; ++c) L += g_pl[b0 + c*64];
    float linv = 1.f / fmaxf(L, 1e-33f);
    float pii = g_dw[(h*16 + it)*64 + row] * linv;
    float alpha = g_c.alpha;
    float ca = 1.f - alpha;
    float cb = alpha / (1.f + pii);
    float outs = g_c.outs[h];

    for (int cc = 0; cc < 16; cc += 4) {
        float ax=0.f, ay=0.f, az=0.f, aw=0.f;
        for (int c = 0; c < nc; ++c) {
            float4 p = *(const float4*)(g_pacc + (size_t)(b0 + c*64)*64 + c0 + cc);
            ax += p.x; ay += p.y; az += p.z; aw += p.w;
        }
        float4 v = *(const float4*)(g_v + (size_t)(h*T_N + i0 + row)*D_N + c0 + cc);
        float4 o;
        float p0 = ax*linv, p1 = ay*linv, p2 = az*linv, p3 = aw*linv;
        o.x = outs * (ca*p0 + cb*(p0 + pii*v.x));
        o.y = outs * (ca*p1 + cb*(p1 + pii*v.y));
        o.z = outs * (ca*p2 + cb*(p2 + pii*v.z));
        o.w = outs * (ca*p3 + cb*(p3 + pii*v.w));
        *(float4*)(g_y + (size_t)(i0 + row)*C_N + h*D_N + c0 + cc) = o;
    }
}

// ---------------- launch ----------------
extern "C" void kernel_launch(void* const* d_in, const int* in_sizes, int n_in,
                              void* d_out, int out_size) {
    const float* x         = (const float*)d_in[0];
    const float* W_qkvg    = (const float*)d_in[1];
    const float* W_out     = (const float*)d_in[2];
    const float* lam       = (const float*)d_in[3];
    const float* log_tau   = (const float*)d_in[4];
    const float* logit_w   = (const float*)d_in[5];
    const float* beta      = (const float*)d_in[6];
    const float* out_scale = (const float*)d_in[7];
    const float* dp_scale  = (const float*)d_in[8];
    const float* logk_sc   = (const float*)d_in[9];
    const float* dt_logit  = (const float*)d_in[10];
    const float* gnw       = (const float*)d_in[11];
    float* out = (float*)d_out;

    float* y_p = nullptr;
    cudaGetSymbolAddress((void**)&y_p, g_y);

    const int G128_SMEM = 2*STG128*4;
    const int G64_SMEM  = 2*STG64*4;
    cudaFuncSetAttribute(gemm_tf32_128, cudaFuncAttributeMaxDynamicSharedMemorySize, G128_SMEM);
    cudaFuncSetAttribute(gemm_tf32_64,  cudaFuncAttributeMaxDynamicSharedMemorySize, G64_SMEM);
    cudaFuncSetAttribute(attn_part, cudaFuncAttributeMaxDynamicSharedMemorySize, ATT_SMEM_BYTES);

    const_kernel<<<1, 32>>>(lam, log_tau, logit_w, beta, out_scale, dp_scale, logk_sc, dt_logit);
    gemm_tf32_128<<<dim3(3072/128, 1024/128), 256, G128_SMEM>>>(x, W_qkvg, nullptr, T_N, 4*C_N, C_N, 1);
    rmsnorm_g<<<(H_N*T_N*32)/256, 256>>>(gnw);
    bound_kernel<<<H_N, 256>>>();
    attn_part<<<480, 256, ATT_SMEM_BYTES>>>();
    attn_combine<<<192, 256>>>();
    gemm_tf32_64<<<dim3(768/128, 1024/64), 256, G64_SMEM>>>(y_p, W_out, out, T_N, C_N, C_N);
}

// round 8
// speedup vs baseline: 1.4985x; 1.0903x over previous
#include <cuda_runtime.h>
#include <cuda_bf16.h>

#define T_N 1024
#define C_N 768
#define H_N 12
#define D_N 64
#define NT_N 8
#define LOG2E 1.4426950408889634f

// ---------------- scratch (static device globals; no allocation) ----------------
__device__ float g_q[H_N * T_N * D_N];       // [H][T][D]
__device__ float g_k[H_N * T_N * D_N];
__device__ float g_v[H_N * T_N * D_N];
__device__ float g_g[H_N * T_N * D_N];       // raw then rmsnormed+tf32-quantized g
__device__ float g_g2[H_N * T_N];            // ||ghat||^2 per (h,t)
__device__ float g_y[T_N * C_N];             // attention out, [T][C] layout
__device__ unsigned g_red[H_N][3];           // per-head max ||q||^2, ||k||^2, g2 (uint-ordered)

// split-j partials: 40 units per head (chunks of <=4 j-tiles), all at scale 2^-M
__device__ float g_pacc[H_N * 40 * 64 * 64]; // [h][unit][row][col]
__device__ float g_pl[H_N * 40 * 64];
__device__ float g_dw[H_N * 16 * 64];        // diag weights per (h,it,row)

// unit tables: heavy (4-tile) units first for scheduling
__constant__ int c_uit[40] = {15,15,15,15,14,14,14,13,13,13,12,12,12,11,11,11,10,10,9,9,8,8,7,7,6,5,4,3,
                              14,10,6,2, 13,9,5,1, 12,8,4,0};
__constant__ int c_uc[40]  = { 0, 1, 2, 3, 0, 1, 2, 0, 1, 2, 0, 1, 2, 0, 1, 2, 0, 1,0,1,0,1,0,1,0,0,0,0,
                               3, 2,1,0,  3,2,1,0,  3,2,1,0};
__constant__ int c_off[16] = {0,1,2,3,4,6,8,10,12,15,18,21,24,28,32,36};

struct Consts {
    float inv4tau[H_N][NT_N];
    float wte[H_N][NT_N];
    float neghb[H_N];
    float dpl[H_N];           // lam * dp_scale/(8*0.8)
    float glk[H_N];           // (1-lam) * logk_scale * ln2
    float outs[H_N];
    float fA[H_N], fB[H_N], i4t0[H_N];
    int   fastf[H_N];
    float alpha;
};
__device__ Consts g_c;

__device__ __forceinline__ float ex2f_(float x){ float y; asm("ex2.approx.ftz.f32 %0, %1;":"=f"(y):"f"(x)); return y; }
__device__ __forceinline__ float lg2f_(float x){ float y; asm("lg2.approx.ftz.f32 %0, %1;":"=f"(y):"f"(x)); return y; }
__device__ __forceinline__ unsigned f2tf32(float x){ unsigned y; asm("cvt.rna.tf32.f32 %0, %1;":"=r"(y):"f"(x)); return y; }

__device__ __forceinline__ void mma_tf32(float* d, const unsigned* a, const unsigned* b) {
    asm volatile(
      "mma.sync.aligned.m16n8k8.row.col.f32.tf32.tf32.f32 "
      "{%0,%1,%2,%3}, {%4,%5,%6,%7}, {%8,%9}, {%0,%1,%2,%3};\n"
      : "+f"(d[0]), "+f"(d[1]), "+f"(d[2]), "+f"(d[3])
      : "r"(a[0]), "r"(a[1]), "r"(a[2]), "r"(a[3]), "r"(b[0]), "r"(b[1]));
}

// ---------------- constants precompute (also zero reduce cells) ----------------
__global__ void const_kernel(const float* lam_p, const float* log_tau,
                             const float* logit_w, const float* beta,
                             const float* out_scale, const float* dp_scale,
                             const float* logk_scale, const float* dt_logit) {
    if (threadIdx.x != 0 || blockIdx.x != 0) return;
    float lam = lam_p[0];
    for (int h = 0; h < H_N; ++h) {
        g_red[h][0] = 0u; g_red[h][1] = 0u; g_red[h][2] = 0u;
        float mx = -1e30f;
        for (int t = 0; t < NT_N; ++t) mx = fmaxf(mx, logit_w[h*NT_N+t]);
        float s = 0.f, e[NT_N];
        for (int t = 0; t < NT_N; ++t) { e[t] = expf(logit_w[h*NT_N+t]-mx); s += e[t]; }
        float W = 0.f;
        for (int t = 0; t < NT_N; ++t) { g_c.wte[h][t] = e[t]/s + 1e-12f; W += g_c.wte[h][t]; }
        for (int t = 0; t < NT_N; ++t) {
            float tau = fmaxf(expf(log_tau[h*NT_N+t]), 1e-6f);
            g_c.inv4tau[h][t] = 1.f/(4.f*tau);
        }
        float bc = fminf(fmaxf(beta[h], 0.5f), 2.5f);
        float neghb = -0.5f*bc;
        float dpc = dp_scale[h]/(8.0f*0.8f);
        float lks = logk_scale[h]*0.6931471805599453f;
        g_c.neghb[h] = neghb;
        g_c.dpl[h]   = lam*dpc;
        g_c.glk[h]   = (1.f-lam)*lks;
        g_c.outs[h]  = out_scale[h];
        int same = 1;
        for (int t = 1; t < NT_N; ++t) if (g_c.inv4tau[h][t] != g_c.inv4tau[h][0]) same = 0;
        g_c.fastf[h] = same;
        g_c.i4t0[h]  = g_c.inv4tau[h][0];
        g_c.fA[h]    = g_c.glk[h]*neghb;
        g_c.fB[h]    = g_c.glk[h]*log2f(W);
    }
    g_c.alpha = 0.1f/(1.f+expf(-dt_logit[0]));
}

// ---------------- parallel norm reduce: one thread per (h,t) row ----------------
__global__ __launch_bounds__(256) void norm_reduce() {
    int gt = blockIdx.x*256 + threadIdx.x;     // 0..12287
    int h = gt >> 10, t = gt & 1023;
    int lane = threadIdx.x & 31;
    const float4* qr = (const float4*)(g_q + ((size_t)h*T_N + t)*D_N);
    const float4* kr = (const float4*)(g_k + ((size_t)h*T_N + t)*D_N);
    float sq = 0.f, sk = 0.f;
    #pragma unroll
    for (int i = 0; i < 16; ++i) {
        float4 a = qr[i], b = kr[i];
        sq += a.x*a.x + a.y*a.y + a.z*a.z + a.w*a.w;
        sk += b.x*b.x + b.y*b.y + b.z*b.z + b.w*b.w;
    }
    float mg = g_g2[h*T_N + t];
    // warps are head-uniform (1024 % 32 == 0) -> warp-reduce then one atomic per warp
    #pragma unroll
    for (int m = 16; m; m >>= 1) {
        sq = fmaxf(sq, __shfl_xor_sync(0xffffffffu, sq, m));
        sk = fmaxf(sk, __shfl_xor_sync(0xffffffffu, sk, m));
        mg = fmaxf(mg, __shfl_xor_sync(0xffffffffu, mg, m));
    }
    if (lane == 0) {
        atomicMax(&g_red[h][0], __float_as_uint(sq));
        atomicMax(&g_red[h][1], __float_as_uint(sk));
        atomicMax(&g_red[h][2], __float_as_uint(mg));
    }
}

// ---------------- tf32 GEMM 128x128, double-buffered; optional qkvg scatter ----------------
#define GS 36
#define STG128 (2*128*GS)   // words per stage (A tile + B tile)

__global__ __launch_bounds__(256, 2) void gemm_tf32_128(const float* __restrict__ A,
        const float* __restrict__ B, float* __restrict__ C, int M, int N, int K, int scatter) {
    extern __shared__ unsigned gsm[];
    int tid = threadIdx.x;
    int lane = tid & 31, w = tid >> 5;
    int wm = w >> 2, wn = w & 3;
    int m0 = blockIdx.y*128, n0 = blockIdx.x*128;
    int lr = tid >> 3, lc = (tid & 7)*4;
    const float* Ap = A + (size_t)(m0+lr)*K + lc;
    const float* Bp = B + (size_t)(n0+lr)*K + lc;

    float acc[4][4][4];
    #pragma unroll
    for (int i = 0; i < 4; ++i)
        #pragma unroll
        for (int j = 0; j < 4; ++j)
            #pragma unroll
            for (int v = 0; v < 4; ++v) acc[i][j][v] = 0.f;

    int qa = lane >> 2, ra = lane & 3;

    float4 pra[4], prb[4];
    #pragma unroll
    for (int p = 0; p < 4; ++p) {
        pra[p] = *(const float4*)(Ap + (size_t)p*32*K);
        prb[p] = *(const float4*)(Bp + (size_t)p*32*K);
    }
    {   // store stage 0
        unsigned* As = gsm;
        unsigned* Bs = gsm + 128*GS;
        #pragma unroll
        for (int p = 0; p < 4; ++p) {
            unsigned* as = As + (lr + p*32)*GS + lc;
            unsigned* bs = Bs + (lr + p*32)*GS + lc;
            as[0]=f2tf32(pra[p].x); as[1]=f2tf32(pra[p].y); as[2]=f2tf32(pra[p].z); as[3]=f2tf32(pra[p].w);
            bs[0]=f2tf32(prb[p].x); bs[1]=f2tf32(prb[p].y); bs[2]=f2tf32(prb[p].z); bs[3]=f2tf32(prb[p].w);
        }
    }
    __syncthreads();
    int cur = 0;

    for (int kb = 0; kb < K; kb += 32) {
        bool nxt = (kb + 32 < K);
        if (nxt) {
            #pragma unroll
            for (int p = 0; p < 4; ++p) {
                pra[p] = *(const float4*)(Ap + (size_t)p*32*K + kb + 32);
                prb[p] = *(const float4*)(Bp + (size_t)p*32*K + kb + 32);
            }
        }
        unsigned* As = gsm + cur*STG128;
        unsigned* Bs = As + 128*GS;
        #pragma unroll
        for (int ks = 0; ks < 4; ++ks) {
            unsigned af[4][4], bf[4][2];
            #pragma unroll
            for (int mt = 0; mt < 4; ++mt) {
                const unsigned* p = As + (wm*64 + mt*16 + qa)*GS + ks*8 + ra;
                af[mt][0] = p[0];
                af[mt][1] = p[8*GS];
                af[mt][2] = p[4];
                af[mt][3] = p[8*GS + 4];
            }
            #pragma unroll
            for (int nt = 0; nt < 4; ++nt) {
                const unsigned* p = Bs + (wn*32 + nt*8 + qa)*GS + ks*8 + ra;
                bf[nt][0] = p[0];
                bf[nt][1] = p[4];
            }
            #pragma unroll
            for (int mt = 0; mt < 4; ++mt)
                #pragma unroll
                for (int nt = 0; nt < 4; ++nt)
                    mma_tf32(acc[mt][nt], af[mt], bf[nt]);
        }
        if (nxt) {
            unsigned* As2 = gsm + (cur^1)*STG128;
            unsigned* Bs2 = As2 + 128*GS;
            #pragma unroll
            for (int p = 0; p < 4; ++p) {
                unsigned* as = As2 + (lr + p*32)*GS + lc;
                unsigned* bs = Bs2 + (lr + p*32)*GS + lc;
                as[0]=f2tf32(pra[p].x); as[1]=f2tf32(pra[p].y); as[2]=f2tf32(pra[p].z); as[3]=f2tf32(pra[p].w);
                bs[0]=f2tf32(prb[p].x); bs[1]=f2tf32(prb[p].y); bs[2]=f2tf32(prb[p].z); bs[3]=f2tf32(prb[p].w);
            }
            __syncthreads();
            cur ^= 1;
        }
    }

    #pragma unroll
    for (int mt = 0; mt < 4; ++mt) {
        int row = m0 + wm*64 + mt*16 + qa;
        #pragma unroll
        for (int nt = 0; nt < 4; ++nt) {
            float2 c0 = {acc[mt][nt][0], acc[mt][nt][1]};
            float2 c1 = {acc[mt][nt][2], acc[mt][nt][3]};
            if (scatter) {
                int colb = n0 + wn*32 + nt*8;      // section & head uniform per fragment
                int sec = colb / C_N;
                int hh = (colb % C_N) >> 6;
                int dd = (colb & 63) + ra*2;
                float* base = (sec == 0) ? g_q : (sec == 1) ? g_k : (sec == 2) ? g_v : g_g;
                *(float2*)(base + ((size_t)(hh*T_N + row)*D_N + dd)) = c0;
                *(float2*)(base + ((size_t)(hh*T_N + row + 8)*D_N + dd)) = c1;
            } else {
                int col = n0 + wn*32 + nt*8 + ra*2;
                *(float2*)(C + (size_t)row*N + col) = c0;
                *(float2*)(C + (size_t)(row+8)*N + col) = c1;
            }
        }
    }
}

// ---------------- tf32 GEMM 64x128 (for out projection) ----------------
#define STG64 ((64+128)*GS)

__global__ __launch_bounds__(256, 2) void gemm_tf32_64(const float* __restrict__ A,
        const float* __restrict__ B, float* __restrict__ C, int M, int N, int K) {
    extern __shared__ unsigned gsm[];
    int tid = threadIdx.x;
    int lane = tid & 31, w = tid >> 5;
    int wm = w >> 2, wn = w & 3;
    int m0 = blockIdx.y*64, n0 = blockIdx.x*128;
    int lr = tid >> 3, lc = (tid & 7)*4;
    const float* Ap = A + (size_t)(m0+lr)*K + lc;
    const float* Bp = B + (size_t)(n0+lr)*K + lc;

    float acc[2][4][4];
    #pragma unroll
    for (int i = 0; i < 2; ++i)
        #pragma unroll
        for (int j = 0; j < 4; ++j)
            #pragma unroll
            for (int v = 0; v < 4; ++v) acc[i][j][v] = 0.f;

    int qa = lane >> 2, ra = lane & 3;

    float4 pra[2], prb[4];
    #pragma unroll
    for (int p = 0; p < 2; ++p) pra[p] = *(const float4*)(Ap + (size_t)p*32*K);
    #pragma unroll
    for (int p = 0; p < 4; ++p) prb[p] = *(const float4*)(Bp + (size_t)p*32*K);
    {
        unsigned* As = gsm;
        unsigned* Bs = gsm + 64*GS;
        #pragma unroll
        for (int p = 0; p < 2; ++p) {
            unsigned* as = As + (lr + p*32)*GS + lc;
            as[0]=f2tf32(pra[p].x); as[1]=f2tf32(pra[p].y); as[2]=f2tf32(pra[p].z); as[3]=f2tf32(pra[p].w);
        }
        #pragma unroll
        for (int p = 0; p < 4; ++p) {
            unsigned* bs = Bs + (lr + p*32)*GS + lc;
            bs[0]=f2tf32(prb[p].x); bs[1]=f2tf32(prb[p].y); bs[2]=f2tf32(prb[p].z); bs[3]=f2tf32(prb[p].w);
        }
    }
    __syncthreads();
    int cur = 0;

    for (int kb = 0; kb < K; kb += 32) {
        bool nxt = (kb + 32 < K);
        if (nxt) {
            #pragma unroll
            for (int p = 0; p < 2; ++p) pra[p] = *(const float4*)(Ap + (size_t)p*32*K + kb + 32);
            #pragma unroll
            for (int p = 0; p < 4; ++p) prb[p] = *(const float4*)(Bp + (size_t)p*32*K + kb + 32);
        }
        unsigned* As = gsm + cur*STG64;
        unsigned* Bs = As + 64*GS;
        #pragma unroll
        for (int ks = 0; ks < 4; ++ks) {
            unsigned af[2][4], bf[4][2];
            #pragma unroll
            for (int mt = 0; mt < 2; ++mt) {
                const unsigned* p = As + (wm*32 + mt*16 + qa)*GS + ks*8 + ra;
                af[mt][0] = p[0];
                af[mt][1] = p[8*GS];
                af[mt][2] = p[4];
                af[mt][3] = p[8*GS + 4];
            }
            #pragma unroll
            for (int nt = 0; nt < 4; ++nt) {
                const unsigned* p = Bs + (wn*32 + nt*8 + qa)*GS + ks*8 + ra;
                bf[nt][0] = p[0];
                bf[nt][1] = p[4];
            }
            #pragma unroll
            for (int mt = 0; mt < 2; ++mt)
                #pragma unroll
                for (int nt = 0; nt < 4; ++nt)
                    mma_tf32(acc[mt][nt], af[mt], bf[nt]);
        }
        if (nxt) {
            unsigned* As2 = gsm + (cur^1)*STG64;
            unsigned* Bs2 = As2 + 64*GS;
            #pragma unroll
            for (int p = 0; p < 2; ++p) {
                unsigned* as = As2 + (lr + p*32)*GS + lc;
                as[0]=f2tf32(pra[p].x); as[1]=f2tf32(pra[p].y); as[2]=f2tf32(pra[p].z); as[3]=f2tf32(pra[p].w);
            }
            #pragma unroll
            for (int p = 0; p < 4; ++p) {
                unsigned* bs = Bs2 + (lr + p*32)*GS + lc;
                bs[0]=f2tf32(prb[p].x); bs[1]=f2tf32(prb[p].y); bs[2]=f2tf32(prb[p].z); bs[3]=f2tf32(prb[p].w);
            }
            __syncthreads();
            cur ^= 1;
        }
    }

    #pragma unroll
    for (int mt = 0; mt < 2; ++mt) {
        int row = m0 + wm*32 + mt*16 + qa;
        #pragma unroll
        for (int nt = 0; nt < 4; ++nt) {
            int col = n0 + wn*32 + nt*8 + ra*2;
            float2 c0 = {acc[mt][nt][0], acc[mt][nt][1]};
            float2 c1 = {acc[mt][nt][2], acc[mt][nt][3]};
            *(float2*)(C + (size_t)row*N + col) = c0;
            *(float2*)(C + (size_t)(row+8)*N + col) = c1;
        }
    }
}

// ---------------- rmsnorm g in place (quantize to tf32) + g2 ----------------
__global__ __launch_bounds__(256) void rmsnorm_g(const float* __restrict__ gnw) {
    int gw = (blockIdx.x*256 + threadIdx.x) >> 5;
    int lane = threadIdx.x & 31;
    if (gw >= H_N*T_N) return;
    float* p = g_g + (size_t)gw*D_N + lane*2;
    float2 gv = *(float2*)p;
    float ss = gv.x*gv.x + gv.y*gv.y;
    #pragma unroll
    for (int m = 16; m; m >>= 1) ss += __shfl_xor_sync(0xffffffffu, ss, m);
    float r = rsqrtf(ss*(1.0f/D_N) + 1e-6f);
    float2 wv = *(const float2*)(gnw + lane*2);
    float q0 = __uint_as_float(f2tf32(gv.x*r*wv.x));
    float q1 = __uint_as_float(f2tf32(gv.y*r*wv.y));
    float2 gq = {q0, q1};
    *(float2*)p = gq;
    float s2 = q0*q0 + q1*q1;
    #pragma unroll
    for (int m = 16; m; m >>= 1) s2 += __shfl_xor_sync(0xffffffffu, s2, m);
    if (lane == 0) g_g2[gw] = s2;
}

// ---------------- split-j flash attention partial (fixed-max, no online softmax) ----------------
#define QS_O   0
#define GI_O   4352
#define KS_O   8704
#define GJ_O   13056
#define VS_O   17408            // 72 rows x 68 (row 64 = ones for row-sum, 65-71 zero)
#define PS_O   22304
#define G2I_O  26656
#define G2J_O  26720
#define DWS_O  26784
#define ATT_SMEM_WORDS 26848
#define ATT_SMEM_BYTES (ATT_SMEM_WORDS*4)

__global__ __launch_bounds__(256, 2) void attn_part() {
    extern __shared__ unsigned smu[];
    float* smf = (float*)smu;
    unsigned* Qs  = smu + QS_O;          // [64][68] tf32
    unsigned* Gis = smu + GI_O;          // [64][68] tf32 (pre-quantized g)
    unsigned* Ks  = smu + KS_O;
    unsigned* Gjs = smu + GJ_O;
    unsigned* Vs  = smu + VS_O;          // [72][68]: d rows 0-63, ones row 64
    unsigned* Ps  = smu + PS_O;
    float* g2i_s = smf + G2I_O;
    float* g2j_s = smf + G2J_O;
    float* dws   = smf + DWS_O;

    int bid = blockIdx.x;
    int h = bid % H_N;
    int u = bid / H_N;
    int it = c_uit[u], cch = c_uc[u];
    int i0 = it * 64;
    int jt0 = cch*4, jt1 = min(jt0+3, it);
    int uidx = c_off[it] + cch;
    int tid = threadIdx.x;
    int lane = tid & 31, w = tid >> 5;
    int wm = w >> 1, wn = w & 1;
    int qa = lane >> 2, ra = lane & 3;
    int row0 = wm*16 + qa;

    int fast = g_c.fastf[h];
    float i4t0 = g_c.i4t0[h];
    float neghb = g_c.neghb[h];

    // ---- derive safe max M from reduced norms (inline, few flops) ----
    float M2;
    {
        float mq = __uint_as_float(g_red[h][0]);
        float mk = __uint_as_float(g_red[h][1]);
        float mg = __uint_as_float(g_red[h][2]);
        float dplL_ = g_c.dpl[h]*LOG2E;
        float bqk = fabsf(dplL_)*sqrtf(mq*mk);
        float smax = 4.f*mg + 1.f;
        float kmax;
        if (fast) {
            float a = g_c.fA[h]*LOG2E, b = g_c.fB[h]*LOG2E;
            float t1 = fmaf(a, log2f(fmaf(smax, i4t0, 1.f)), b);
            kmax = fmaxf(t1, b);
        } else {
            float glkL_ = g_c.glk[h]*LOG2E;
            float W = 0.f, Kmin = 0.f;
            #pragma unroll
            for (int t = 0; t < NT_N; ++t) {
                W += g_c.wte[h][t];
                Kmin += g_c.wte[h][t]*powf(fmaf(smax, g_c.inv4tau[h][t], 1.f), neghb);
            }
            kmax = fmaxf(glkL_*log2f(W), glkL_*log2f(Kmin));
        }
        M2 = bqk + kmax + 1.f;
    }
    float dplL = g_c.dpl[h]*LOG2E;
    float fAL  = g_c.fA[h]*LOG2E;
    float fBM  = g_c.fB[h]*LOG2E - M2;
    float glkL = g_c.glk[h]*LOG2E;
    float mneg = -M2;

    const float* qg  = g_q + (size_t)(h*T_N + i0)*D_N;
    const float* gig = g_g + (size_t)(h*T_N + i0)*D_N;
    #pragma unroll
    for (int p = 0; p < 4; ++p) {
        int e = tid + p*256;
        int r = e >> 4, dc = (e & 15)*4;
        float4 a = *(const float4*)(qg + r*D_N + dc);
        uint4 ua; ua.x=f2tf32(a.x); ua.y=f2tf32(a.y); ua.z=f2tf32(a.z); ua.w=f2tf32(a.w);
        *(uint4*)(Qs + r*68 + dc) = ua;
        float4 b = *(const float4*)(gig + r*D_N + dc);
        uint4 ub; ub.x=__float_as_uint(b.x); ub.y=__float_as_uint(b.y);
        ub.z=__float_as_uint(b.z); ub.w=__float_as_uint(b.w);   // already tf32-quantized
        *(uint4*)(Gis + r*68 + dc) = ub;
    }
    if (tid < 64) g2i_s[tid] = g_g2[h*T_N + i0 + tid];
    // ones row (64) + zero rows (65-71) of Vs — written once, never overwritten
    for (int z = tid; z < 8*68; z += 256)
        Vs[64*68 + z] = (z < 64) ? f2tf32(1.f) : 0u;

    float apv[5][4];
    #pragma unroll
    for (int nt = 0; nt < 5; ++nt)
        #pragma unroll
        for (int c = 0; c < 4; ++c) apv[nt][c] = 0.f;

    for (int jt = jt0; jt <= jt1; ++jt) {
        int j0 = jt*64;
        __syncthreads();   // prev tile's Ps/Vs reads done
        const float* kg  = g_k + (size_t)(h*T_N + j0)*D_N;
        const float* gjg = g_g + (size_t)(h*T_N + j0)*D_N;
        const float* vg  = g_v + (size_t)(h*T_N + j0)*D_N;
        #pragma unroll
        for (int p = 0; p < 4; ++p) {
            int e = tid + p*256;
            int r = e >> 4, dc = (e & 15)*4;
            float4 a = *(const float4*)(kg + r*D_N + dc);
            uint4 ua; ua.x=f2tf32(a.x); ua.y=f2tf32(a.y); ua.z=f2tf32(a.z); ua.w=f2tf32(a.w);
            *(uint4*)(Ks + r*68 + dc) = ua;
            float4 b = *(const float4*)(gjg + r*D_N + dc);
            uint4 ub; ub.x=__float_as_uint(b.x); ub.y=__float_as_uint(b.y);
            ub.z=__float_as_uint(b.z); ub.w=__float_as_uint(b.w);
            *(uint4*)(Gjs + r*68 + dc) = ub;
            int j = e & 63, dg = (e >> 6)*4;
            float4 v = *(const float4*)(vg + j*D_N + dg);
            Vs[(dg+0)*68 + j] = f2tf32(v.x);
            Vs[(dg+1)*68 + j] = f2tf32(v.y);
            Vs[(dg+2)*68 + j] = f2tf32(v.z);
            Vs[(dg+3)*68 + j] = f2tf32(v.w);
        }
        if (tid < 64) g2j_s[tid] = g_g2[h*T_N + j0 + tid];
        __syncthreads();

        // ---- QK + GG MMAs ----
        float dqk[4][4], dgg[4][4];
        #pragma unroll
        for (int nt = 0; nt < 4; ++nt)
            #pragma unroll
            for (int c = 0; c < 4; ++c) { dqk[nt][c] = 0.f; dgg[nt][c] = 0.f; }

        #pragma unroll
        for (int ks = 0; ks < 8; ++ks) {
            int kc = ks*8 + ra;
            const unsigned* qp = Qs + row0*68 + kc;
            unsigned af[4] = {qp[0], qp[8*68], qp[4], qp[8*68+4]};
            const unsigned* gp = Gis + row0*68 + kc;
            unsigned gf[4] = {gp[0], gp[8*68], gp[4], gp[8*68+4]};
            #pragma unroll
            for (int nt = 0; nt < 4; ++nt) {
                int nb = wn*32 + nt*8 + qa;
                const unsigned* kp = Ks + nb*68 + kc;
                unsigned bf[2] = {kp[0], kp[4]};
                const unsigned* gjp = Gjs + nb*68 + kc;
                unsigned bgf[2] = {gjp[0], gjp[4]};
                mma_tf32(dqk[nt], af, bf);
                mma_tf32(dgg[nt], gf, bgf);
            }
        }

        // ---- epilogue: p = 2^(score - M), no running max, no row exchange ----
        int diag = (jt == it);
        #pragma unroll
        for (int nt = 0; nt < 4; ++nt) {
            #pragma unroll
            for (int c = 0; c < 4; ++c) {
                int rh = c >> 1, pp = c & 1;
                int rl = row0 + rh*8;
                int cl = wn*32 + nt*8 + 2*ra + pp;
                float p = 0.f;
                if (j0 + cl <= i0 + rl) {
                    float s = fmaxf(g2i_s[rl] + g2j_s[cl] - 2.f*dgg[nt][c], 0.f);
                    float blc;
                    if (fast) {
                        blc = fmaf(dqk[nt][c], dplL, fmaf(fAL, lg2f_(fmaf(s, i4t0, 1.f)), fBM));
                    } else {
                        float Ksum = 0.f;
                        #pragma unroll
                        for (int t = 0; t < 8; ++t) {
                            float uu = fmaf(s, g_c.inv4tau[h][t], 1.f);
                            Ksum = fmaf(g_c.wte[h][t], ex2f_(neghb * lg2f_(uu)), Ksum);
                        }
                        blc = fmaf(dqk[nt][c], dplL, fmaf(glkL, lg2f_(Ksum), mneg));
                    }
                    p = ex2f_(blc);
                }
                dqk[nt][c] = p;
            }
            int cl = wn*32 + nt*8 + 2*ra;
            float p00 = dqk[nt][0], p01 = dqk[nt][1];
            float p10 = dqk[nt][2], p11 = dqk[nt][3];
            if (diag) {
                if (row0 == cl) dws[row0] = p00; else if (row0 == cl+1) dws[row0] = p01;
                if (row0+8 == cl) dws[row0+8] = p10; else if (row0+8 == cl+1) dws[row0+8] = p11;
            }
            uint2 s0; s0.x = f2tf32(p00); s0.y = f2tf32(p01);
            uint2 s1; s1.x = f2tf32(p10); s1.y = f2tf32(p11);
            *(uint2*)(Ps + row0*68 + cl) = s0;
            *(uint2*)(Ps + (row0+8)*68 + cl) = s1;
        }
        __syncthreads();   // Ps visible

        // ---- PV MMAs (k=64; wn==1 adds ones-column for row-sum l) ----
        #pragma unroll
        for (int ks = 0; ks < 8; ++ks) {
            int kc = ks*8 + ra;
            const unsigned* pp_ = Ps + row0*68 + kc;
            unsigned pf[4] = {pp_[0], pp_[8*68], pp_[4], pp_[8*68+4]};
            #pragma unroll
            for (int nt = 0; nt < 5; ++nt) {
                if (nt == 4 && wn == 0) break;
                const unsigned* vp = Vs + (wn*32 + nt*8 + qa)*68 + kc;
                unsigned vf[2] = {vp[0], vp[4]};
                mma_tf32(apv[nt], pf, vf);
            }
        }
    }

    // ---- write partials (all at common scale 2^-M, no merge needed) ----
    int base = (h*40 + uidx)*64;
    #pragma unroll
    for (int nt = 0; nt < 4; ++nt) {
        int cl = wn*32 + nt*8 + 2*ra;
        float2 a0 = {apv[nt][0], apv[nt][1]};
        float2 a1 = {apv[nt][2], apv[nt][3]};
        *(float2*)(g_pacc + (size_t)(base + row0)*64 + cl) = a0;
        *(float2*)(g_pacc + (size_t)(base + row0 + 8)*64 + cl) = a1;
    }
    if (wn == 1 && ra == 0) {
        g_pl[base + row0]     = apv[4][0];
        g_pl[base + row0 + 8] = apv[4][2];
    }
    if (jt1 == it && tid < 64) g_dw[(h*16 + it)*64 + tid] = dws[tid];
}

// ---------------- combine partials -> g_y (same-scale: plain sums) ----------------
__global__ __launch_bounds__(256) void attn_combine() {
    int bid = blockIdx.x;
    int h = bid % H_N, it = bid / H_N;
    int i0 = it * 64;
    int nc = it/4 + 1;
    int tid = threadIdx.x;
    int row = tid >> 2;
    int c0 = (tid & 3) * 16;
    int b0 = (h*40 + c_off[it])*64 + row;

    float L = 0.f;
    for (int c = 0; c < nc; ++c) L += g_pl[b0 + c*64];
    float linv = 1.f / fmaxf(L, 1e-33f);
    float pii = g_dw[(h*16 + it)*64 + row] * linv;
    float alpha = g_c.alpha;
    float ca = 1.f - alpha;
    float cb = alpha / (1.f + pii);
    float outs = g_c.outs[h];

    for (int cc = 0; cc < 16; cc += 4) {
        float ax=0.f, ay=0.f, az=0.f, aw=0.f;
        for (int c = 0; c < nc; ++c) {
            float4 p = *(const float4*)(g_pacc + (size_t)(b0 + c*64)*64 + c0 + cc);
            ax += p.x; ay += p.y; az += p.z; aw += p.w;
        }
        float4 v = *(const float4*)(g_v + (size_t)(h*T_N + i0 + row)*D_N + c0 + cc);
        float4 o;
        float p0 = ax*linv, p1 = ay*linv, p2 = az*linv, p3 = aw*linv;
        o.x = outs * (ca*p0 + cb*(p0 + pii*v.x));
        o.y = outs * (ca*p1 + cb*(p1 + pii*v.y));
        o.z = outs * (ca*p2 + cb*(p2 + pii*v.z));
        o.w = outs * (ca*p3 + cb*(p3 + pii*v.w));
        *(float4*)(g_y + (size_t)(i0 + row)*C_N + h*D_N + c0 + cc) = o;
    }
}

// ---------------- launch ----------------
extern "C" void kernel_launch(void* const* d_in, const int* in_sizes, int n_in,
                              void* d_out, int out_size) {
    const float* x         = (const float*)d_in[0];
    const float* W_qkvg    = (const float*)d_in[1];
    const float* W_out     = (const float*)d_in[2];
    const float* lam       = (const float*)d_in[3];
    const float* log_tau   = (const float*)d_in[4];
    const float* logit_w   = (const float*)d_in[5];
    const float* beta      = (const float*)d_in[6];
    const float* out_scale = (const float*)d_in[7];
    const float* dp_scale  = (const float*)d_in[8];
    const float* logk_sc   = (const float*)d_in[9];
    const float* dt_logit  = (const float*)d_in[10];
    const float* gnw       = (const float*)d_in[11];
    float* out = (float*)d_out;

    float* y_p = nullptr;
    cudaGetSymbolAddress((void**)&y_p, g_y);

    const int G128_SMEM = 2*STG128*4;
    const int G64_SMEM  = 2*STG64*4;
    cudaFuncSetAttribute(gemm_tf32_128, cudaFuncAttributeMaxDynamicSharedMemorySize, G128_SMEM);
    cudaFuncSetAttribute(gemm_tf32_64,  cudaFuncAttributeMaxDynamicSharedMemorySize, G64_SMEM);
    cudaFuncSetAttribute(attn_part, cudaFuncAttributeMaxDynamicSharedMemorySize, ATT_SMEM_BYTES);

    const_kernel<<<1, 32>>>(lam, log_tau, logit_w, beta, out_scale, dp_scale, logk_sc, dt_logit);
    gemm_tf32_128<<<dim3(3072/128, 1024/128), 256, G128_SMEM>>>(x, W_qkvg, nullptr, T_N, 4*C_N, C_N, 1);
    rmsnorm_g<<<(H_N*T_N*32)/256, 256>>>(gnw);
    norm_reduce<<<(H_N*T_N)/256, 256>>>();
    attn_part<<<480, 256, ATT_SMEM_BYTES>>>();
    attn_combine<<<192, 256>>>();
    gemm_tf32_64<<<dim3(768/128, 1024/64), 256, G64_SMEM>>>(y_p, W_out, out, T_N, C_N, C_N);
}

// round 9
// speedup vs baseline: 1.7128x; 1.1430x over previous
#include <cuda_runtime.h>
#include <cuda_bf16.h>

#define T_N 1024
#define C_N 768
#define H_N 12
#define D_N 64
#define NT_N 8
#define LOG2E 1.4426950408889634f

// ---------------- scratch (static device globals; no allocation) ----------------
__device__ float g_q[H_N * T_N * D_N];       // [H][T][D]
__device__ float g_k[H_N * T_N * D_N];
__device__ float g_v[H_N * T_N * D_N];
__device__ float g_g[H_N * T_N * D_N];       // raw then rmsnormed+tf32-quantized g
__device__ float g_g2[H_N * T_N];            // ||ghat||^2 per (h,t)
__device__ float g_y[T_N * C_N];             // attention out, [T][C] layout
__device__ unsigned g_red[H_N][3];           // per-head max ||q||^2, ||k||^2, g2 (uint-ordered)

// split-j partials: 40 units per head (chunks of <=4 j-tiles), all at scale 2^-M
__device__ float g_pacc[H_N * 40 * 64 * 64]; // [h][unit][row][col]
__device__ float g_pl[H_N * 40 * 64];
__device__ float g_dw[H_N * 16 * 64];        // diag weights per (h,it,row)

// unit tables: heavy (4-tile) units first for scheduling
__constant__ int c_uit[40] = {15,15,15,15,14,14,14,13,13,13,12,12,12,11,11,11,10,10,9,9,8,8,7,7,6,5,4,3,
                              14,10,6,2, 13,9,5,1, 12,8,4,0};
__constant__ int c_uc[40]  = { 0, 1, 2, 3, 0, 1, 2, 0, 1, 2, 0, 1, 2, 0, 1, 2, 0, 1,0,1,0,1,0,1,0,0,0,0,
                               3, 2,1,0,  3,2,1,0,  3,2,1,0};
__constant__ int c_off[16] = {0,1,2,3,4,6,8,10,12,15,18,21,24,28,32,36};

struct Consts {
    float inv4tau[H_N][NT_N];
    float wte[H_N][NT_N];
    float neghb[H_N];
    float dpl[H_N];           // lam * dp_scale/(8*0.8)
    float glk[H_N];           // (1-lam) * logk_scale * ln2
    float outs[H_N];
    float fA[H_N], fB[H_N], i4t0[H_N];
    int   fastf[H_N];
    float alpha;
};
__device__ Consts g_c;

__device__ __forceinline__ float ex2f_(float x){ float y; asm("ex2.approx.ftz.f32 %0, %1;":"=f"(y):"f"(x)); return y; }
__device__ __forceinline__ float lg2f_(float x){ float y; asm("lg2.approx.ftz.f32 %0, %1;":"=f"(y):"f"(x)); return y; }
__device__ __forceinline__ unsigned f2tf32(float x){ unsigned y; asm("cvt.rna.tf32.f32 %0, %1;":"=r"(y):"f"(x)); return y; }

__device__ __forceinline__ void mma_tf32(float* d, const unsigned* a, const unsigned* b) {
    asm volatile(
      "mma.sync.aligned.m16n8k8.row.col.f32.tf32.tf32.f32 "
      "{%0,%1,%2,%3}, {%4,%5,%6,%7}, {%8,%9}, {%0,%1,%2,%3};\n"
      : "+f"(d[0]), "+f"(d[1]), "+f"(d[2]), "+f"(d[3])
      : "r"(a[0]), "r"(a[1]), "r"(a[2]), "r"(a[3]), "r"(b[0]), "r"(b[1]));
}

// ---------------- constants precompute (parallel over heads; zero reduce cells) ----------------
__global__ void const_kernel(const float* lam_p, const float* log_tau,
                             const float* logit_w, const float* beta,
                             const float* out_scale, const float* dp_scale,
                             const float* logk_scale, const float* dt_logit) {
    int h = threadIdx.x;
    if (blockIdx.x != 0 || h >= H_N) return;
    float lam = lam_p[0];
    g_red[h][0] = 0u; g_red[h][1] = 0u; g_red[h][2] = 0u;
    float mx = -1e30f;
    for (int t = 0; t < NT_N; ++t) mx = fmaxf(mx, logit_w[h*NT_N+t]);
    float s = 0.f, e[NT_N];
    for (int t = 0; t < NT_N; ++t) { e[t] = expf(logit_w[h*NT_N+t]-mx); s += e[t]; }
    float W = 0.f;
    for (int t = 0; t < NT_N; ++t) { g_c.wte[h][t] = e[t]/s + 1e-12f; W += g_c.wte[h][t]; }
    for (int t = 0; t < NT_N; ++t) {
        float tau = fmaxf(expf(log_tau[h*NT_N+t]), 1e-6f);
        g_c.inv4tau[h][t] = 1.f/(4.f*tau);
    }
    float bc = fminf(fmaxf(beta[h], 0.5f), 2.5f);
    float neghb = -0.5f*bc;
    float dpc = dp_scale[h]/(8.0f*0.8f);
    float lks = logk_scale[h]*0.6931471805599453f;
    g_c.neghb[h] = neghb;
    g_c.dpl[h]   = lam*dpc;
    g_c.glk[h]   = (1.f-lam)*lks;
    g_c.outs[h]  = out_scale[h];
    int same = 1;
    for (int t = 1; t < NT_N; ++t) if (g_c.inv4tau[h][t] != g_c.inv4tau[h][0]) same = 0;
    g_c.fastf[h] = same;
    g_c.i4t0[h]  = g_c.inv4tau[h][0];
    g_c.fA[h]    = g_c.glk[h]*neghb;
    g_c.fB[h]    = g_c.glk[h]*log2f(W);
    if (h == 0) g_c.alpha = 0.1f/(1.f+expf(-dt_logit[0]));
}

// ---------------- tf32 GEMM 128x128, double-buffered; optional qkvg scatter ----------------
#define GS 36
#define STG128 (2*128*GS)   // words per stage (A tile + B tile)

__global__ __launch_bounds__(256, 2) void gemm_tf32_128(const float* __restrict__ A,
        const float* __restrict__ B, float* __restrict__ C, int M, int N, int K, int scatter) {
    extern __shared__ unsigned gsm[];
    int tid = threadIdx.x;
    int lane = tid & 31, w = tid >> 5;
    int wm = w >> 2, wn = w & 3;
    int m0 = blockIdx.y*128, n0 = blockIdx.x*128;
    int lr = tid >> 3, lc = (tid & 7)*4;
    const float* Ap = A + (size_t)(m0+lr)*K + lc;
    const float* Bp = B + (size_t)(n0+lr)*K + lc;

    float acc[4][4][4];
    #pragma unroll
    for (int i = 0; i < 4; ++i)
        #pragma unroll
        for (int j = 0; j < 4; ++j)
            #pragma unroll
            for (int v = 0; v < 4; ++v) acc[i][j][v] = 0.f;

    int qa = lane >> 2, ra = lane & 3;

    float4 pra[4], prb[4];
    #pragma unroll
    for (int p = 0; p < 4; ++p) {
        pra[p] = *(const float4*)(Ap + (size_t)p*32*K);
        prb[p] = *(const float4*)(Bp + (size_t)p*32*K);
    }
    {   // store stage 0
        unsigned* As = gsm;
        unsigned* Bs = gsm + 128*GS;
        #pragma unroll
        for (int p = 0; p < 4; ++p) {
            unsigned* as = As + (lr + p*32)*GS + lc;
            unsigned* bs = Bs + (lr + p*32)*GS + lc;
            as[0]=f2tf32(pra[p].x); as[1]=f2tf32(pra[p].y); as[2]=f2tf32(pra[p].z); as[3]=f2tf32(pra[p].w);
            bs[0]=f2tf32(prb[p].x); bs[1]=f2tf32(prb[p].y); bs[2]=f2tf32(prb[p].z); bs[3]=f2tf32(prb[p].w);
        }
    }
    __syncthreads();
    int cur = 0;

    for (int kb = 0; kb < K; kb += 32) {
        bool nxt = (kb + 32 < K);
        if (nxt) {
            #pragma unroll
            for (int p = 0; p < 4; ++p) {
                pra[p] = *(const float4*)(Ap + (size_t)p*32*K + kb + 32);
                prb[p] = *(const float4*)(Bp + (size_t)p*32*K + kb + 32);
            }
        }
        unsigned* As = gsm + cur*STG128;
        unsigned* Bs = As + 128*GS;
        #pragma unroll
        for (int ks = 0; ks < 4; ++ks) {
            unsigned af[4][4], bf[4][2];
            #pragma unroll
            for (int mt = 0; mt < 4; ++mt) {
                const unsigned* p = As + (wm*64 + mt*16 + qa)*GS + ks*8 + ra;
                af[mt][0] = p[0];
                af[mt][1] = p[8*GS];
                af[mt][2] = p[4];
                af[mt][3] = p[8*GS + 4];
            }
            #pragma unroll
            for (int nt = 0; nt < 4; ++nt) {
                const unsigned* p = Bs + (wn*32 + nt*8 + qa)*GS + ks*8 + ra;
                bf[nt][0] = p[0];
                bf[nt][1] = p[4];
            }
            #pragma unroll
            for (int mt = 0; mt < 4; ++mt)
                #pragma unroll
                for (int nt = 0; nt < 4; ++nt)
                    mma_tf32(acc[mt][nt], af[mt], bf[nt]);
        }
        if (nxt) {
            unsigned* As2 = gsm + (cur^1)*STG128;
            unsigned* Bs2 = As2 + 128*GS;
            #pragma unroll
            for (int p = 0; p < 4; ++p) {
                unsigned* as = As2 + (lr + p*32)*GS + lc;
                unsigned* bs = Bs2 + (lr + p*32)*GS + lc;
                as[0]=f2tf32(pra[p].x); as[1]=f2tf32(pra[p].y); as[2]=f2tf32(pra[p].z); as[3]=f2tf32(pra[p].w);
                bs[0]=f2tf32(prb[p].x); bs[1]=f2tf32(prb[p].y); bs[2]=f2tf32(prb[p].z); bs[3]=f2tf32(prb[p].w);
            }
            __syncthreads();
            cur ^= 1;
        }
    }

    #pragma unroll
    for (int mt = 0; mt < 4; ++mt) {
        int row = m0 + wm*64 + mt*16 + qa;
        #pragma unroll
        for (int nt = 0; nt < 4; ++nt) {
            float2 c0 = {acc[mt][nt][0], acc[mt][nt][1]};
            float2 c1 = {acc[mt][nt][2], acc[mt][nt][3]};
            if (scatter) {
                int colb = n0 + wn*32 + nt*8;      // section & head uniform per fragment
                int sec = colb / C_N;
                int hh = (colb % C_N) >> 6;
                int dd = (colb & 63) + ra*2;
                float* base = (sec == 0) ? g_q : (sec == 1) ? g_k : (sec == 2) ? g_v : g_g;
                *(float2*)(base + ((size_t)(hh*T_N + row)*D_N + dd)) = c0;
                *(float2*)(base + ((size_t)(hh*T_N + row + 8)*D_N + dd)) = c1;
            } else {
                int col = n0 + wn*32 + nt*8 + ra*2;
                *(float2*)(C + (size_t)row*N + col) = c0;
                *(float2*)(C + (size_t)(row+8)*N + col) = c1;
            }
        }
    }
}

// ---------------- tf32 GEMM 64x128 (for out projection) ----------------
#define STG64 ((64+128)*GS)

__global__ __launch_bounds__(256, 2) void gemm_tf32_64(const float* __restrict__ A,
        const float* __restrict__ B, float* __restrict__ C, int M, int N, int K) {
    extern __shared__ unsigned gsm[];
    int tid = threadIdx.x;
    int lane = tid & 31, w = tid >> 5;
    int wm = w >> 2, wn = w & 3;
    int m0 = blockIdx.y*64, n0 = blockIdx.x*128;
    int lr = tid >> 3, lc = (tid & 7)*4;
    const float* Ap = A + (size_t)(m0+lr)*K + lc;
    const float* Bp = B + (size_t)(n0+lr)*K + lc;

    float acc[2][4][4];
    #pragma unroll
    for (int i = 0; i < 2; ++i)
        #pragma unroll
        for (int j = 0; j < 4; ++j)
            #pragma unroll
            for (int v = 0; v < 4; ++v) acc[i][j][v] = 0.f;

    int qa = lane >> 2, ra = lane & 3;

    float4 pra[2], prb[4];
    #pragma unroll
    for (int p = 0; p < 2; ++p) pra[p] = *(const float4*)(Ap + (size_t)p*32*K);
    #pragma unroll
    for (int p = 0; p < 4; ++p) prb[p] = *(const float4*)(Bp + (size_t)p*32*K);
    {
        unsigned* As = gsm;
        unsigned* Bs = gsm + 64*GS;
        #pragma unroll
        for (int p = 0; p < 2; ++p) {
            unsigned* as = As + (lr + p*32)*GS + lc;
            as[0]=f2tf32(pra[p].x); as[1]=f2tf32(pra[p].y); as[2]=f2tf32(pra[p].z); as[3]=f2tf32(pra[p].w);
        }
        #pragma unroll
        for (int p = 0; p < 4; ++p) {
            unsigned* bs = Bs + (lr + p*32)*GS + lc;
            bs[0]=f2tf32(prb[p].x); bs[1]=f2tf32(prb[p].y); bs[2]=f2tf32(prb[p].z); bs[3]=f2tf32(prb[p].w);
        }
    }
    __syncthreads();
    int cur = 0;

    for (int kb = 0; kb < K; kb += 32) {
        bool nxt = (kb + 32 < K);
        if (nxt) {
            #pragma unroll
            for (int p = 0; p < 2; ++p) pra[p] = *(const float4*)(Ap + (size_t)p*32*K + kb + 32);
            #pragma unroll
            for (int p = 0; p < 4; ++p) prb[p] = *(const float4*)(Bp + (size_t)p*32*K + kb + 32);
        }
        unsigned* As = gsm + cur*STG64;
        unsigned* Bs = As + 64*GS;
        #pragma unroll
        for (int ks = 0; ks < 4; ++ks) {
            unsigned af[2][4], bf[4][2];
            #pragma unroll
            for (int mt = 0; mt < 2; ++mt) {
                const unsigned* p = As + (wm*32 + mt*16 + qa)*GS + ks*8 + ra;
                af[mt][0] = p[0];
                af[mt][1] = p[8*GS];
                af[mt][2] = p[4];
                af[mt][3] = p[8*GS + 4];
            }
            #pragma unroll
            for (int nt = 0; nt < 4; ++nt) {
                const unsigned* p = Bs + (wn*32 + nt*8 + qa)*GS + ks*8 + ra;
                bf[nt][0] = p[0];
                bf[nt][1] = p[4];
            }
            #pragma unroll
            for (int mt = 0; mt < 2; ++mt)
                #pragma unroll
                for (int nt = 0; nt < 4; ++nt)
                    mma_tf32(acc[mt][nt], af[mt], bf[nt]);
        }
        if (nxt) {
            unsigned* As2 = gsm + (cur^1)*STG64;
            unsigned* Bs2 = As2 + 64*GS;
            #pragma unroll
            for (int p = 0; p < 2; ++p) {
                unsigned* as = As2 + (lr + p*32)*GS + lc;
                as[0]=f2tf32(pra[p].x); as[1]=f2tf32(pra[p].y); as[2]=f2tf32(pra[p].z); as[3]=f2tf32(pra[p].w);
            }
            #pragma unroll
            for (int p = 0; p < 4; ++p) {
                unsigned* bs = Bs2 + (lr + p*32)*GS + lc;
                bs[0]=f2tf32(prb[p].x); bs[1]=f2tf32(prb[p].y); bs[2]=f2tf32(prb[p].z); bs[3]=f2tf32(prb[p].w);
            }
            __syncthreads();
            cur ^= 1;
        }
    }

    #pragma unroll
    for (int mt = 0; mt < 2; ++mt) {
        int row = m0 + wm*32 + mt*16 + qa;
        #pragma unroll
        for (int nt = 0; nt < 4; ++nt) {
            int col = n0 + wn*32 + nt*8 + ra*2;
            float2 c0 = {acc[mt][nt][0], acc[mt][nt][1]};
            float2 c1 = {acc[mt][nt][2], acc[mt][nt][3]};
            *(float2*)(C + (size_t)row*N + col) = c0;
            *(float2*)(C + (size_t)(row+8)*N + col) = c1;
        }
    }
}

// ---------------- rmsnorm g in place (quantize to tf32) + g2 + fused norm maxes ----------------
// One warp per (h,t) row; 8 rows per block (all same head). Block-reduce then 3 atomics.
__global__ __launch_bounds__(256) void rmsnorm_g(const float* __restrict__ gnw) {
    __shared__ float smax[3][8];
    int gw = (blockIdx.x*256 + threadIdx.x) >> 5;   // row 0..12287, grid exact
    int lane = threadIdx.x & 31;
    int wid = threadIdx.x >> 5;
    int h = gw >> 10;
    float* p = g_g + (size_t)gw*D_N + lane*2;
    float2 gv = *(float2*)p;
    float ss = gv.x*gv.x + gv.y*gv.y;
    #pragma unroll
    for (int m = 16; m; m >>= 1) ss += __shfl_xor_sync(0xffffffffu, ss, m);
    float r = rsqrtf(ss*(1.0f/D_N) + 1e-6f);
    float2 wv = *(const float2*)(gnw + lane*2);
    float q0 = __uint_as_float(f2tf32(gv.x*r*wv.x));
    float q1 = __uint_as_float(f2tf32(gv.y*r*wv.y));
    float2 gq = {q0, q1};
    *(float2*)p = gq;
    // fused: q/k row norms + g2
    float2 qv2 = *(const float2*)(g_q + (size_t)gw*D_N + lane*2);
    float2 kv2 = *(const float2*)(g_k + (size_t)gw*D_N + lane*2);
    float s2 = q0*q0 + q1*q1;
    float sq = qv2.x*qv2.x + qv2.y*qv2.y;
    float sk = kv2.x*kv2.x + kv2.y*kv2.y;
    #pragma unroll
    for (int m = 16; m; m >>= 1) {
        s2 += __shfl_xor_sync(0xffffffffu, s2, m);
        sq += __shfl_xor_sync(0xffffffffu, sq, m);
        sk += __shfl_xor_sync(0xffffffffu, sk, m);
    }
    if (lane == 0) {
        g_g2[gw] = s2;
        smax[0][wid] = sq; smax[1][wid] = sk; smax[2][wid] = s2;
    }
    __syncthreads();
    if (threadIdx.x < 3) {
        float mx = 0.f;
        #pragma unroll
        for (int i = 0; i < 8; ++i) mx = fmaxf(mx, smax[threadIdx.x][i]);
        atomicMax(&g_red[h][threadIdx.x], __float_as_uint(mx));
    }
}

// ---------------- split-j flash attention partial (fixed-max, no online softmax) ----------------
#define QS_O   0
#define GI_O   4352
#define KS_O   8704
#define GJ_O   13056
#define VS_O   17408            // 72 rows x 68 (row 64 = ones for row-sum, 65-71 zero)
#define PS_O   22304
#define G2I_O  26656
#define G2J_O  26720
#define DWS_O  26784
#define ATT_SMEM_WORDS 26848
#define ATT_SMEM_BYTES (ATT_SMEM_WORDS*4)

__global__ __launch_bounds__(256, 2) void attn_part() {
    extern __shared__ unsigned smu[];
    float* smf = (float*)smu;
    unsigned* Qs  = smu + QS_O;          // [64][68] tf32
    unsigned* Gis = smu + GI_O;          // [64][68] tf32 (pre-quantized g)
    unsigned* Ks  = smu + KS_O;
    unsigned* Gjs = smu + GJ_O;
    unsigned* Vs  = smu + VS_O;          // [72][68]: d rows 0-63, ones row 64
    unsigned* Ps  = smu + PS_O;
    float* g2i_s = smf + G2I_O;
    float* g2j_s = smf + G2J_O;
    float* dws   = smf + DWS_O;

    int bid = blockIdx.x;
    int h = bid % H_N;
    int u = bid / H_N;
    int it = c_uit[u], cch = c_uc[u];
    int i0 = it * 64;
    int jt0 = cch*4, jt1 = min(jt0+3, it);
    int uidx = c_off[it] + cch;
    int tid = threadIdx.x;
    int lane = tid & 31, w = tid >> 5;
    int wm = w >> 1, wn = w & 1;
    int qa = lane >> 2, ra = lane & 3;
    int row0 = wm*16 + qa;

    int fast = g_c.fastf[h];
    float i4t0 = g_c.i4t0[h];
    float neghb = g_c.neghb[h];

    // ---- derive safe max M from reduced norms (inline, few flops) ----
    float M2;
    {
        float mq = __uint_as_float(g_red[h][0]);
        float mk = __uint_as_float(g_red[h][1]);
        float mg = __uint_as_float(g_red[h][2]);
        float dplL_ = g_c.dpl[h]*LOG2E;
        float bqk = fabsf(dplL_)*sqrtf(mq*mk);
        float smax = 4.f*mg + 1.f;
        float kmax;
        if (fast) {
            float a = g_c.fA[h]*LOG2E, b = g_c.fB[h]*LOG2E;
            float t1 = fmaf(a, log2f(fmaf(smax, i4t0, 1.f)), b);
            kmax = fmaxf(t1, b);
        } else {
            float glkL_ = g_c.glk[h]*LOG2E;
            float W = 0.f, Kmin = 0.f;
            #pragma unroll
            for (int t = 0; t < NT_N; ++t) {
                W += g_c.wte[h][t];
                Kmin += g_c.wte[h][t]*powf(fmaf(smax, g_c.inv4tau[h][t], 1.f), neghb);
            }
            kmax = fmaxf(glkL_*log2f(W), glkL_*log2f(Kmin));
        }
        M2 = bqk + kmax + 1.f;
    }
    float dplL = g_c.dpl[h]*LOG2E;
    float fAL  = g_c.fA[h]*LOG2E;
    float fBM  = g_c.fB[h]*LOG2E - M2;
    float glkL = g_c.glk[h]*LOG2E;
    float mneg = -M2;

    const float* qg  = g_q + (size_t)(h*T_N + i0)*D_N;
    const float* gig = g_g + (size_t)(h*T_N + i0)*D_N;
    #pragma unroll
    for (int p = 0; p < 4; ++p) {
        int e = tid + p*256;
        int r = e >> 4, dc = (e & 15)*4;
        float4 a = *(const float4*)(qg + r*D_N + dc);
        uint4 ua; ua.x=f2tf32(a.x); ua.y=f2tf32(a.y); ua.z=f2tf32(a.z); ua.w=f2tf32(a.w);
        *(uint4*)(Qs + r*68 + dc) = ua;
        float4 b = *(const float4*)(gig + r*D_N + dc);
        uint4 ub; ub.x=__float_as_uint(b.x); ub.y=__float_as_uint(b.y);
        ub.z=__float_as_uint(b.z); ub.w=__float_as_uint(b.w);   // already tf32-quantized
        *(uint4*)(Gis + r*68 + dc) = ub;
    }
    if (tid < 64) g2i_s[tid] = g_g2[h*T_N + i0 + tid];
    // ones row (64) + zero rows (65-71) of Vs — written once, never overwritten
    for (int z = tid; z < 8*68; z += 256)
        Vs[64*68 + z] = (z < 64) ? f2tf32(1.f) : 0u;

    float apv[5][4];
    #pragma unroll
    for (int nt = 0; nt < 5; ++nt)
        #pragma unroll
        for (int c = 0; c < 4; ++c) apv[nt][c] = 0.f;

    for (int jt = jt0; jt <= jt1; ++jt) {
        int j0 = jt*64;
        __syncthreads();   // prev tile's Ps/Vs reads done
        const float* kg  = g_k + (size_t)(h*T_N + j0)*D_N;
        const float* gjg = g_g + (size_t)(h*T_N + j0)*D_N;
        const float* vg  = g_v + (size_t)(h*T_N + j0)*D_N;
        #pragma unroll
        for (int p = 0; p < 4; ++p) {
            int e = tid + p*256;
            int r = e >> 4, dc = (e & 15)*4;
            float4 a = *(const float4*)(kg + r*D_N + dc);
            uint4 ua; ua.x=f2tf32(a.x); ua.y=f2tf32(a.y); ua.z=f2tf32(a.z); ua.w=f2tf32(a.w);
            *(uint4*)(Ks + r*68 + dc) = ua;
            float4 b = *(const float4*)(gjg + r*D_N + dc);
            uint4 ub; ub.x=__float_as_uint(b.x); ub.y=__float_as_uint(b.y);
            ub.z=__float_as_uint(b.z); ub.w=__float_as_uint(b.w);
            *(uint4*)(Gjs + r*68 + dc) = ub;
            int j = e & 63, dg = (e >> 6)*4;
            float4 v = *(const float4*)(vg + j*D_N + dg);
            Vs[(dg+0)*68 + j] = f2tf32(v.x);
            Vs[(dg+1)*68 + j] = f2tf32(v.y);
            Vs[(dg+2)*68 + j] = f2tf32(v.z);
            Vs[(dg+3)*68 + j] = f2tf32(v.w);
        }
        if (tid < 64) g2j_s[tid] = g_g2[h*T_N + j0 + tid];
        __syncthreads();

        // ---- QK + GG MMAs ----
        float dqk[4][4], dgg[4][4];
        #pragma unroll
        for (int nt = 0; nt < 4; ++nt)
            #pragma unroll
            for (int c = 0; c < 4; ++c) { dqk[nt][c] = 0.f; dgg[nt][c] = 0.f; }

        #pragma unroll
        for (int ks = 0; ks < 8; ++ks) {
            int kc = ks*8 + ra;
            const unsigned* qp = Qs + row0*68 + kc;
            unsigned af[4] = {qp[0], qp[8*68], qp[4], qp[8*68+4]};
            const unsigned* gp = Gis + row0*68 + kc;
            unsigned gf[4] = {gp[0], gp[8*68], gp[4], gp[8*68+4]};
            #pragma unroll
            for (int nt = 0; nt < 4; ++nt) {
                int nb = wn*32 + nt*8 + qa;
                const unsigned* kp = Ks + nb*68 + kc;
                unsigned bf[2] = {kp[0], kp[4]};
                const unsigned* gjp = Gjs + nb*68 + kc;
                unsigned bgf[2] = {gjp[0], gjp[4]};
                mma_tf32(dqk[nt], af, bf);
                mma_tf32(dgg[nt], gf, bgf);
            }
        }

        // ---- epilogue: p = 2^(score - M), no running max, no row exchange ----
        int diag = (jt == it);
        #pragma unroll
        for (int nt = 0; nt < 4; ++nt) {
            #pragma unroll
            for (int c = 0; c < 4; ++c) {
                int rh = c >> 1, pp = c & 1;
                int rl = row0 + rh*8;
                int cl = wn*32 + nt*8 + 2*ra + pp;
                float p = 0.f;
                if (j0 + cl <= i0 + rl) {
                    float s = fmaxf(g2i_s[rl] + g2j_s[cl] - 2.f*dgg[nt][c], 0.f);
                    float blc;
                    if (fast) {
                        blc = fmaf(dqk[nt][c], dplL, fmaf(fAL, lg2f_(fmaf(s, i4t0, 1.f)), fBM));
                    } else {
                        float Ksum = 0.f;
                        #pragma unroll
                        for (int t = 0; t < 8; ++t) {
                            float uu = fmaf(s, g_c.inv4tau[h][t], 1.f);
                            Ksum = fmaf(g_c.wte[h][t], ex2f_(neghb * lg2f_(uu)), Ksum);
                        }
                        blc = fmaf(dqk[nt][c], dplL, fmaf(glkL, lg2f_(Ksum), mneg));
                    }
                    p = ex2f_(blc);
                }
                dqk[nt][c] = p;
            }
            int cl = wn*32 + nt*8 + 2*ra;
            float p00 = dqk[nt][0], p01 = dqk[nt][1];
            float p10 = dqk[nt][2], p11 = dqk[nt][3];
            if (diag) {
                if (row0 == cl) dws[row0] = p00; else if (row0 == cl+1) dws[row0] = p01;
                if (row0+8 == cl) dws[row0+8] = p10; else if (row0+8 == cl+1) dws[row0+8] = p11;
            }
            uint2 s0; s0.x = f2tf32(p00); s0.y = f2tf32(p01);
            uint2 s1; s1.x = f2tf32(p10); s1.y = f2tf32(p11);
            *(uint2*)(Ps + row0*68 + cl) = s0;
            *(uint2*)(Ps + (row0+8)*68 + cl) = s1;
        }
        __syncthreads();   // Ps visible

        // ---- PV MMAs (k=64; wn==1 adds ones-column for row-sum l) ----
        #pragma unroll
        for (int ks = 0; ks < 8; ++ks) {
            int kc = ks*8 + ra;
            const unsigned* pp_ = Ps + row0*68 + kc;
            unsigned pf[4] = {pp_[0], pp_[8*68], pp_[4], pp_[8*68+4]};
            #pragma unroll
            for (int nt = 0; nt < 5; ++nt) {
                if (nt == 4 && wn == 0) break;
                const unsigned* vp = Vs + (wn*32 + nt*8 + qa)*68 + kc;
                unsigned vf[2] = {vp[0], vp[4]};
                mma_tf32(apv[nt], pf, vf);
            }
        }
    }

    // ---- write partials (all at common scale 2^-M, no merge needed) ----
    int base = (h*40 + uidx)*64;
    #pragma unroll
    for (int nt = 0; nt < 4; ++nt) {
        int cl = wn*32 + nt*8 + 2*ra;
        float2 a0 = {apv[nt][0], apv[nt][1]};
        float2 a1 = {apv[nt][2], apv[nt][3]};
        *(float2*)(g_pacc + (size_t)(base + row0)*64 + cl) = a0;
        *(float2*)(g_pacc + (size_t)(base + row0 + 8)*64 + cl) = a1;
    }
    if (wn == 1 && ra == 0) {
        g_pl[base + row0]     = apv[4][0];
        g_pl[base + row0 + 8] = apv[4][2];
    }
    if (jt1 == it && tid < 64) g_dw[(h*16 + it)*64 + tid] = dws[tid];
}

// ---------------- combine partials -> g_y (same-scale: plain sums) ----------------
__global__ __launch_bounds__(256) void attn_combine() {
    int bid = blockIdx.x;
    int h = bid % H_N, it = bid / H_N;
    int i0 = it * 64;
    int nc = it/4 + 1;
    int tid = threadIdx.x;
    int row = tid >> 2;
    int c0 = (tid & 3) * 16;
    int b0 = (h*40 + c_off[it])*64 + row;

    float L = 0.f;
    for (int c = 0; c < nc; ++c) L += g_pl[b0 + c*64];
    float linv = 1.f / fmaxf(L, 1e-33f);
    float pii = g_dw[(h*16 + it)*64 + row] * linv;
    float alpha = g_c.alpha;
    float ca = 1.f - alpha;
    float cb = alpha / (1.f + pii);
    float outs = g_c.outs[h];

    for (int cc = 0; cc < 16; cc += 4) {
        float ax=0.f, ay=0.f, az=0.f, aw=0.f;
        for (int c = 0; c < nc; ++c) {
            float4 p = *(const float4*)(g_pacc + (size_t)(b0 + c*64)*64 + c0 + cc);
            ax += p.x; ay += p.y; az += p.z; aw += p.w;
        }
        float4 v = *(const float4*)(g_v + (size_t)(h*T_N + i0 + row)*D_N + c0 + cc);
        float4 o;
        float p0 = ax*linv, p1 = ay*linv, p2 = az*linv, p3 = aw*linv;
        o.x = outs * (ca*p0 + cb*(p0 + pii*v.x));
        o.y = outs * (ca*p1 + cb*(p1 + pii*v.y));
        o.z = outs * (ca*p2 + cb*(p2 + pii*v.z));
        o.w = outs * (ca*p3 + cb*(p3 + pii*v.w));
        *(float4*)(g_y + (size_t)(i0 + row)*C_N + h*D_N + c0 + cc) = o;
    }
}

// ---------------- launch ----------------
extern "C" void kernel_launch(void* const* d_in, const int* in_sizes, int n_in,
                              void* d_out, int out_size) {
    const float* x         = (const float*)d_in[0];
    const float* W_qkvg    = (const float*)d_in[1];
    const float* W_out     = (const float*)d_in[2];
    const float* lam       = (const float*)d_in[3];
    const float* log_tau   = (const float*)d_in[4];
    const float* logit_w   = (const float*)d_in[5];
    const float* beta      = (const float*)d_in[6];
    const float* out_scale = (const float*)d_in[7];
    const float* dp_scale  = (const float*)d_in[8];
    const float* logk_sc   = (const float*)d_in[9];
    const float* dt_logit  = (const float*)d_in[10];
    const float* gnw       = (const float*)d_in[11];
    float* out = (float*)d_out;

    float* y_p = nullptr;
    cudaGetSymbolAddress((void**)&y_p, g_y);

    const int G128_SMEM = 2*STG128*4;
    const int G64_SMEM  = 2*STG64*4;
    cudaFuncSetAttribute(gemm_tf32_128, cudaFuncAttributeMaxDynamicSharedMemorySize, G128_SMEM);
    cudaFuncSetAttribute(gemm_tf32_64,  cudaFuncAttributeMaxDynamicSharedMemorySize, G64_SMEM);
    cudaFuncSetAttribute(attn_part, cudaFuncAttributeMaxDynamicSharedMemorySize, ATT_SMEM_BYTES);

    const_kernel<<<1, 32>>>(lam, log_tau, logit_w, beta, out_scale, dp_scale, logk_sc, dt_logit);
    gemm_tf32_128<<<dim3(3072/128, 1024/128), 256, G128_SMEM>>>(x, W_qkvg, nullptr, T_N, 4*C_N, C_N, 1);
    rmsnorm_g<<<(H_N*T_N*32)/256, 256>>>(gnw);
    attn_part<<<480, 256, ATT_SMEM_BYTES>>>();
    attn_combine<<<192, 256>>>();
    gemm_tf32_64<<<dim3(768/128, 1024/64), 256, G64_SMEM>>>(y_p, W_out, out, T_N, C_N, C_N);
}

// round 10
// speedup vs baseline: 1.7428x; 1.0175x over previous
#include <cuda_runtime.h>
#include <cuda_bf16.h>

#define T_N 1024
#define C_N 768
#define H_N 12
#define D_N 64
#define NT_N 8
#define LOG2E 1.4426950408889634f

// ---------------- scratch (static device globals; no allocation) ----------------
__device__ float g_q[H_N * T_N * D_N];       // [H][T][D]
__device__ float g_k[H_N * T_N * D_N];
__device__ float g_v[H_N * T_N * D_N];
__device__ float g_g[H_N * T_N * D_N];       // raw then rmsnormed+tf32-quantized g
__device__ float g_g2[H_N * T_N];            // ||ghat||^2 per (h,t)
__device__ float g_y[T_N * C_N];             // attention out, [T][C] layout
__device__ unsigned g_red[H_N][3];           // per-head max ||q||^2, ||k||^2, g2 (uint-ordered)
__device__ float g_op[3 * T_N * C_N];        // split-k partials for out projection

// split-j partials: 72 units per head (chunks of <=2 j-tiles), all at scale 2^-M
__device__ float g_pacc[H_N * 72 * 64 * 64]; // [h][unit][row][col]
__device__ float g_pl[H_N * 72 * 64];
__device__ float g_dw[H_N * 16 * 64];        // diag weights per (h,it,row)

// unit tables: 2-tile units first (heavy), then 1-tile remainders
__constant__ int c_uit[72] = {
    15,15,15,15,15,15,15,15, 14,14,14,14,14,14,14, 13,13,13,13,13,13,13,
    12,12,12,12,12,12, 11,11,11,11,11,11, 10,10,10,10,10, 9,9,9,9,9,
    8,8,8,8, 7,7,7,7, 6,6,6, 5,5,5, 4,4, 3,3, 2, 1,
    14,12,10,8,6,4,2,0};
__constant__ int c_uc[72] = {
    0,1,2,3,4,5,6,7, 0,1,2,3,4,5,6, 0,1,2,3,4,5,6,
    0,1,2,3,4,5, 0,1,2,3,4,5, 0,1,2,3,4, 0,1,2,3,4,
    0,1,2,3, 0,1,2,3, 0,1,2, 0,1,2, 0,1, 0,1, 0, 0,
    7,6,5,4,3,2,1,0};
__constant__ int c_off[16] = {0,1,2,4,6,9,12,16,20,25,30,36,42,49,56,64};

struct Consts {
    float inv4tau[H_N][NT_N];
    float wte[H_N][NT_N];
    float neghb[H_N];
    float dpl[H_N];           // lam * dp_scale/(8*0.8)
    float glk[H_N];           // (1-lam) * logk_scale * ln2
    float outs[H_N];
    float fA[H_N], fB[H_N], i4t0[H_N];
    int   fastf[H_N];
    float alpha;
};
__device__ Consts g_c;

__device__ __forceinline__ float ex2f_(float x){ float y; asm("ex2.approx.ftz.f32 %0, %1;":"=f"(y):"f"(x)); return y; }
__device__ __forceinline__ float lg2f_(float x){ float y; asm("lg2.approx.ftz.f32 %0, %1;":"=f"(y):"f"(x)); return y; }
__device__ __forceinline__ unsigned f2tf32(float x){ unsigned y; asm("cvt.rna.tf32.f32 %0, %1;":"=r"(y):"f"(x)); return y; }

__device__ __forceinline__ void mma_tf32(float* d, const unsigned* a, const unsigned* b) {
    asm volatile(
      "mma.sync.aligned.m16n8k8.row.col.f32.tf32.tf32.f32 "
      "{%0,%1,%2,%3}, {%4,%5,%6,%7}, {%8,%9}, {%0,%1,%2,%3};\n"
      : "+f"(d[0]), "+f"(d[1]), "+f"(d[2]), "+f"(d[3])
      : "r"(a[0]), "r"(a[1]), "r"(a[2]), "r"(a[3]), "r"(b[0]), "r"(b[1]));
}

// ---------------- constants precompute (parallel over heads; zero reduce cells) ----------------
__global__ void const_kernel(const float* lam_p, const float* log_tau,
                             const float* logit_w, const float* beta,
                             const float* out_scale, const float* dp_scale,
                             const float* logk_scale, const float* dt_logit) {
    int h = threadIdx.x;
    if (blockIdx.x != 0 || h >= H_N) return;
    float lam = lam_p[0];
    g_red[h][0] = 0u; g_red[h][1] = 0u; g_red[h][2] = 0u;
    float mx = -1e30f;
    for (int t = 0; t < NT_N; ++t) mx = fmaxf(mx, logit_w[h*NT_N+t]);
    float s = 0.f, e[NT_N];
    for (int t = 0; t < NT_N; ++t) { e[t] = expf(logit_w[h*NT_N+t]-mx); s += e[t]; }
    float W = 0.f;
    for (int t = 0; t < NT_N; ++t) { g_c.wte[h][t] = e[t]/s + 1e-12f; W += g_c.wte[h][t]; }
    for (int t = 0; t < NT_N; ++t) {
        float tau = fmaxf(expf(log_tau[h*NT_N+t]), 1e-6f);
        g_c.inv4tau[h][t] = 1.f/(4.f*tau);
    }
    float bc = fminf(fmaxf(beta[h], 0.5f), 2.5f);
    float neghb = -0.5f*bc;
    float dpc = dp_scale[h]/(8.0f*0.8f);
    float lks = logk_scale[h]*0.6931471805599453f;
    g_c.neghb[h] = neghb;
    g_c.dpl[h]   = lam*dpc;
    g_c.glk[h]   = (1.f-lam)*lks;
    g_c.outs[h]  = out_scale[h];
    int same = 1;
    for (int t = 1; t < NT_N; ++t) if (g_c.inv4tau[h][t] != g_c.inv4tau[h][0]) same = 0;
    g_c.fastf[h] = same;
    g_c.i4t0[h]  = g_c.inv4tau[h][0];
    g_c.fA[h]    = g_c.glk[h]*neghb;
    g_c.fB[h]    = g_c.glk[h]*log2f(W);
    if (h == 0) g_c.alpha = 0.1f/(1.f+expf(-dt_logit[0]));
}

// ---------------- tf32 GEMM 64x128, double-buffered, k-range, optional qkvg scatter ----------------
#define GS 36
#define STG64 ((64+128)*GS)

__global__ __launch_bounds__(256, 2) void gemm_tf32_64(const float* __restrict__ A,
        const float* __restrict__ B, float* __restrict__ C, int M, int N, int Kst,
        int klen, int scatter) {
    extern __shared__ unsigned gsm[];
    int tid = threadIdx.x;
    int lane = tid & 31, w = tid >> 5;
    int wm = w >> 2, wn = w & 3;
    int m0 = blockIdx.y*64, n0 = blockIdx.x*128;
    int k0 = blockIdx.z*klen;
    int lr = tid >> 3, lc = (tid & 7)*4;
    const float* Ap = A + (size_t)(m0+lr)*Kst + k0 + lc;
    const float* Bp = B + (size_t)(n0+lr)*Kst + k0 + lc;

    float acc[2][4][4];
    #pragma unroll
    for (int i = 0; i < 2; ++i)
        #pragma unroll
        for (int j = 0; j < 4; ++j)
            #pragma unroll
            for (int v = 0; v < 4; ++v) acc[i][j][v] = 0.f;

    int qa = lane >> 2, ra = lane & 3;

    float4 pra[2], prb[4];
    #pragma unroll
    for (int p = 0; p < 2; ++p) pra[p] = *(const float4*)(Ap + (size_t)p*32*Kst);
    #pragma unroll
    for (int p = 0; p < 4; ++p) prb[p] = *(const float4*)(Bp + (size_t)p*32*Kst);
    {
        unsigned* As = gsm;
        unsigned* Bs = gsm + 64*GS;
        #pragma unroll
        for (int p = 0; p < 2; ++p) {
            unsigned* as = As + (lr + p*32)*GS + lc;
            as[0]=f2tf32(pra[p].x); as[1]=f2tf32(pra[p].y); as[2]=f2tf32(pra[p].z); as[3]=f2tf32(pra[p].w);
        }
        #pragma unroll
        for (int p = 0; p < 4; ++p) {
            unsigned* bs = Bs + (lr + p*32)*GS + lc;
            bs[0]=f2tf32(prb[p].x); bs[1]=f2tf32(prb[p].y); bs[2]=f2tf32(prb[p].z); bs[3]=f2tf32(prb[p].w);
        }
    }
    __syncthreads();
    int cur = 0;

    for (int kb = 0; kb < klen; kb += 32) {
        bool nxt = (kb + 32 < klen);
        if (nxt) {
            #pragma unroll
            for (int p = 0; p < 2; ++p) pra[p] = *(const float4*)(Ap + (size_t)p*32*Kst + kb + 32);
            #pragma unroll
            for (int p = 0; p < 4; ++p) prb[p] = *(const float4*)(Bp + (size_t)p*32*Kst + kb + 32);
        }
        unsigned* As = gsm + cur*STG64;
        unsigned* Bs = As + 64*GS;
        #pragma unroll
        for (int ks = 0; ks < 4; ++ks) {
            unsigned af[2][4], bf[4][2];
            #pragma unroll
            for (int mt = 0; mt < 2; ++mt) {
                const unsigned* p = As + (wm*32 + mt*16 + qa)*GS + ks*8 + ra;
                af[mt][0] = p[0];
                af[mt][1] = p[8*GS];
                af[mt][2] = p[4];
                af[mt][3] = p[8*GS + 4];
            }
            #pragma unroll
            for (int nt = 0; nt < 4; ++nt) {
                const unsigned* p = Bs + (wn*32 + nt*8 + qa)*GS + ks*8 + ra;
                bf[nt][0] = p[0];
                bf[nt][1] = p[4];
            }
            #pragma unroll
            for (int mt = 0; mt < 2; ++mt)
                #pragma unroll
                for (int nt = 0; nt < 4; ++nt)
                    mma_tf32(acc[mt][nt], af[mt], bf[nt]);
        }
        if (nxt) {
            unsigned* As2 = gsm + (cur^1)*STG64;
            unsigned* Bs2 = As2 + 64*GS;
            #pragma unroll
            for (int p = 0; p < 2; ++p) {
                unsigned* as = As2 + (lr + p*32)*GS + lc;
                as[0]=f2tf32(pra[p].x); as[1]=f2tf32(pra[p].y); as[2]=f2tf32(pra[p].z); as[3]=f2tf32(pra[p].w);
            }
            #pragma unroll
            for (int p = 0; p < 4; ++p) {
                unsigned* bs = Bs2 + (lr + p*32)*GS + lc;
                bs[0]=f2tf32(prb[p].x); bs[1]=f2tf32(prb[p].y); bs[2]=f2tf32(prb[p].z); bs[3]=f2tf32(prb[p].w);
            }
            __syncthreads();
            cur ^= 1;
        }
    }

    float* Cp = C + (size_t)blockIdx.z*M*N;
    #pragma unroll
    for (int mt = 0; mt < 2; ++mt) {
        int row = m0 + wm*32 + mt*16 + qa;
        #pragma unroll
        for (int nt = 0; nt < 4; ++nt) {
            float2 c0 = {acc[mt][nt][0], acc[mt][nt][1]};
            float2 c1 = {acc[mt][nt][2], acc[mt][nt][3]};
            if (scatter) {
                int colb = n0 + wn*32 + nt*8;      // section & head uniform per fragment
                int sec = colb / C_N;
                int hh = (colb % C_N) >> 6;
                int dd = (colb & 63) + ra*2;
                float* base = (sec == 0) ? g_q : (sec == 1) ? g_k : (sec == 2) ? g_v : g_g;
                *(float2*)(base + ((size_t)(hh*T_N + row)*D_N + dd)) = c0;
                *(float2*)(base + ((size_t)(hh*T_N + row + 8)*D_N + dd)) = c1;
            } else {
                int col = n0 + wn*32 + nt*8 + ra*2;
                *(float2*)(Cp + (size_t)row*N + col) = c0;
                *(float2*)(Cp + (size_t)(row+8)*N + col) = c1;
            }
        }
    }
}

// ---------------- split-k add: out = p0 + p1 + p2 ----------------
__global__ __launch_bounds__(256) void addk_kernel(float* __restrict__ out) {
    int i = blockIdx.x*256 + threadIdx.x;     // float4 index, grid exact
    const float4* p0 = (const float4*)g_op;
    const float4* p1 = (const float4*)(g_op + T_N*C_N);
    const float4* p2 = (const float4*)(g_op + 2*T_N*C_N);
    float4 a = p0[i], b = p1[i], c = p2[i];
    float4 o;
    o.x = a.x + b.x + c.x;
    o.y = a.y + b.y + c.y;
    o.z = a.z + b.z + c.z;
    o.w = a.w + b.w + c.w;
    ((float4*)out)[i] = o;
}

// ---------------- rmsnorm g in place (quantize to tf32) + g2 + fused norm maxes ----------------
__global__ __launch_bounds__(256) void rmsnorm_g(const float* __restrict__ gnw) {
    __shared__ float smax[3][8];
    int gw = (blockIdx.x*256 + threadIdx.x) >> 5;   // row 0..12287, grid exact
    int lane = threadIdx.x & 31;
    int wid = threadIdx.x >> 5;
    int h = gw >> 10;
    float* p = g_g + (size_t)gw*D_N + lane*2;
    float2 gv = *(float2*)p;
    float ss = gv.x*gv.x + gv.y*gv.y;
    #pragma unroll
    for (int m = 16; m; m >>= 1) ss += __shfl_xor_sync(0xffffffffu, ss, m);
    float r = rsqrtf(ss*(1.0f/D_N) + 1e-6f);
    float2 wv = *(const float2*)(gnw + lane*2);
    float q0 = __uint_as_float(f2tf32(gv.x*r*wv.x));
    float q1 = __uint_as_float(f2tf32(gv.y*r*wv.y));
    float2 gq = {q0, q1};
    *(float2*)p = gq;
    float2 qv2 = *(const float2*)(g_q + (size_t)gw*D_N + lane*2);
    float2 kv2 = *(const float2*)(g_k + (size_t)gw*D_N + lane*2);
    float s2 = q0*q0 + q1*q1;
    float sq = qv2.x*qv2.x + qv2.y*qv2.y;
    float sk = kv2.x*kv2.x + kv2.y*kv2.y;
    #pragma unroll
    for (int m = 16; m; m >>= 1) {
        s2 += __shfl_xor_sync(0xffffffffu, s2, m);
        sq += __shfl_xor_sync(0xffffffffu, sq, m);
        sk += __shfl_xor_sync(0xffffffffu, sk, m);
    }
    if (lane == 0) {
        g_g2[gw] = s2;
        smax[0][wid] = sq; smax[1][wid] = sk; smax[2][wid] = s2;
    }
    __syncthreads();
    if (threadIdx.x < 3) {
        float mx = 0.f;
        #pragma unroll
        for (int i = 0; i < 8; ++i) mx = fmaxf(mx, smax[threadIdx.x][i]);
        atomicMax(&g_red[h][threadIdx.x], __float_as_uint(mx));
    }
}

// ---------------- split-j flash attention partial (fixed-max, no online softmax) ----------------
#define QS_O   0
#define GI_O   4352
#define KS_O   8704
#define GJ_O   13056
#define VS_O   17408            // 72 rows x 68 (row 64 = ones for row-sum, 65-71 zero)
#define PS_O   22304
#define G2I_O  26656
#define G2J_O  26720
#define DWS_O  26784
#define ATT_SMEM_WORDS 26848
#define ATT_SMEM_BYTES (ATT_SMEM_WORDS*4)

__global__ __launch_bounds__(256, 2) void attn_part() {
    extern __shared__ unsigned smu[];
    float* smf = (float*)smu;
    unsigned* Qs  = smu + QS_O;          // [64][68] tf32
    unsigned* Gis = smu + GI_O;          // [64][68] tf32 (pre-quantized g)
    unsigned* Ks  = smu + KS_O;
    unsigned* Gjs = smu + GJ_O;
    unsigned* Vs  = smu + VS_O;          // [72][68]: d rows 0-63, ones row 64
    unsigned* Ps  = smu + PS_O;
    float* g2i_s = smf + G2I_O;
    float* g2j_s = smf + G2J_O;
    float* dws   = smf + DWS_O;

    int bid = blockIdx.x;
    int h = bid % H_N;
    int u = bid / H_N;
    int it = c_uit[u], cch = c_uc[u];
    int i0 = it * 64;
    int jt0 = cch*2, jt1 = min(jt0+1, it);
    int uidx = c_off[it] + cch;
    int tid = threadIdx.x;
    int lane = tid & 31, w = tid >> 5;
    int wm = w >> 1, wn = w & 1;
    int qa = lane >> 2, ra = lane & 3;
    int row0 = wm*16 + qa;

    int fast = g_c.fastf[h];
    float i4t0 = g_c.i4t0[h];
    float neghb = g_c.neghb[h];

    // ---- derive safe max M from reduced norms (inline, few flops) ----
    float M2;
    {
        float mq = __uint_as_float(g_red[h][0]);
        float mk = __uint_as_float(g_red[h][1]);
        float mg = __uint_as_float(g_red[h][2]);
        float dplL_ = g_c.dpl[h]*LOG2E;
        float bqk = fabsf(dplL_)*sqrtf(mq*mk);
        float smax = 4.f*mg + 1.f;
        float kmax;
        if (fast) {
            float a = g_c.fA[h]*LOG2E, b = g_c.fB[h]*LOG2E;
            float t1 = fmaf(a, log2f(fmaf(smax, i4t0, 1.f)), b);
            kmax = fmaxf(t1, b);
        } else {
            float glkL_ = g_c.glk[h]*LOG2E;
            float W = 0.f, Kmin = 0.f;
            #pragma unroll
            for (int t = 0; t < NT_N; ++t) {
                W += g_c.wte[h][t];
                Kmin += g_c.wte[h][t]*powf(fmaf(smax, g_c.inv4tau[h][t], 1.f), neghb);
            }
            kmax = fmaxf(glkL_*log2f(W), glkL_*log2f(Kmin));
        }
        M2 = bqk + kmax + 1.f;
    }
    float dplL = g_c.dpl[h]*LOG2E;
    float fAL  = g_c.fA[h]*LOG2E;
    float fBM  = g_c.fB[h]*LOG2E - M2;
    float glkL = g_c.glk[h]*LOG2E;
    float mneg = -M2;

    const float* qg  = g_q + (size_t)(h*T_N + i0)*D_N;
    const float* gig = g_g + (size_t)(h*T_N + i0)*D_N;
    #pragma unroll
    for (int p = 0; p < 4; ++p) {
        int e = tid + p*256;
        int r = e >> 4, dc = (e & 15)*4;
        float4 a = *(const float4*)(qg + r*D_N + dc);
        uint4 ua; ua.x=f2tf32(a.x); ua.y=f2tf32(a.y); ua.z=f2tf32(a.z); ua.w=f2tf32(a.w);
        *(uint4*)(Qs + r*68 + dc) = ua;
        float4 b = *(const float4*)(gig + r*D_N + dc);
        uint4 ub; ub.x=__float_as_uint(b.x); ub.y=__float_as_uint(b.y);
        ub.z=__float_as_uint(b.z); ub.w=__float_as_uint(b.w);   // already tf32-quantized
        *(uint4*)(Gis + r*68 + dc) = ub;
    }
    if (tid < 64) g2i_s[tid] = g_g2[h*T_N + i0 + tid];
    // ones row (64) + zero rows (65-71) of Vs — written once, never overwritten
    for (int z = tid; z < 8*68; z += 256)
        Vs[64*68 + z] = (z < 64) ? f2tf32(1.f) : 0u;

    float apv[5][4];
    #pragma unroll
    for (int nt = 0; nt < 5; ++nt)
        #pragma unroll
        for (int c = 0; c < 4; ++c) apv[nt][c] = 0.f;

    for (int jt = jt0; jt <= jt1; ++jt) {
        int j0 = jt*64;
        __syncthreads();   // prev tile's Ps/Vs reads done
        const float* kg  = g_k + (size_t)(h*T_N + j0)*D_N;
        const float* gjg = g_g + (size_t)(h*T_N + j0)*D_N;
        const float* vg  = g_v + (size_t)(h*T_N + j0)*D_N;
        #pragma unroll
        for (int p = 0; p < 4; ++p) {
            int e = tid + p*256;
            int r = e >> 4, dc = (e & 15)*4;
            float4 a = *(const float4*)(kg + r*D_N + dc);
            uint4 ua; ua.x=f2tf32(a.x); ua.y=f2tf32(a.y); ua.z=f2tf32(a.z); ua.w=f2tf32(a.w);
            *(uint4*)(Ks + r*68 + dc) = ua;
            float4 b = *(const float4*)(gjg + r*D_N + dc);
            uint4 ub; ub.x=__float_as_uint(b.x); ub.y=__float_as_uint(b.y);
            ub.z=__float_as_uint(b.z); ub.w=__float_as_uint(b.w);
            *(uint4*)(Gjs + r*68 + dc) = ub;
            int j = e & 63, dg = (e >> 6)*4;
            float4 v = *(const float4*)(vg + j*D_N + dg);
            Vs[(dg+0)*68 + j] = f2tf32(v.x);
            Vs[(dg+1)*68 + j] = f2tf32(v.y);
            Vs[(dg+2)*68 + j] = f2tf32(v.z);
            Vs[(dg+3)*68 + j] = f2tf32(v.w);
        }
        if (tid < 64) g2j_s[tid] = g_g2[h*T_N + j0 + tid];
        __syncthreads();

        // ---- QK + GG MMAs ----
        float dqk[4][4], dgg[4][4];
        #pragma unroll
        for (int nt = 0; nt < 4; ++nt)
            #pragma unroll
            for (int c = 0; c < 4; ++c) { dqk[nt][c] = 0.f; dgg[nt][c] = 0.f; }

        #pragma unroll
        for (int ks = 0; ks < 8; ++ks) {
            int kc = ks*8 + ra;
            const unsigned* qp = Qs + row0*68 + kc;
            unsigned af[4] = {qp[0], qp[8*68], qp[4], qp[8*68+4]};
            const unsigned* gp = Gis + row0*68 + kc;
            unsigned gf[4] = {gp[0], gp[8*68], gp[4], gp[8*68+4]};
            #pragma unroll
            for (int nt = 0; nt < 4; ++nt) {
                int nb = wn*32 + nt*8 + qa;
                const unsigned* kp = Ks + nb*68 + kc;
                unsigned bf[2] = {kp[0], kp[4]};
                const unsigned* gjp = Gjs + nb*68 + kc;
                unsigned bgf[2] = {gjp[0], gjp[4]};
                mma_tf32(dqk[nt], af, bf);
                mma_tf32(dgg[nt], gf, bgf);
            }
        }

        // ---- epilogue: p = 2^(score - M), no running max, no row exchange ----
        int diag = (jt == it);
        #pragma unroll
        for (int nt = 0; nt < 4; ++nt) {
            #pragma unroll
            for (int c = 0; c < 4; ++c) {
                int rh = c >> 1, pp = c & 1;
                int rl = row0 + rh*8;
                int cl = wn*32 + nt*8 + 2*ra + pp;
                float p = 0.f;
                if (j0 + cl <= i0 + rl) {
                    float s = fmaxf(g2i_s[rl] + g2j_s[cl] - 2.f*dgg[nt][c], 0.f);
                    float blc;
                    if (fast) {
                        blc = fmaf(dqk[nt][c], dplL, fmaf(fAL, lg2f_(fmaf(s, i4t0, 1.f)), fBM));
                    } else {
                        float Ksum = 0.f;
                        #pragma unroll
                        for (int t = 0; t < 8; ++t) {
                            float uu = fmaf(s, g_c.inv4tau[h][t], 1.f);
                            Ksum = fmaf(g_c.wte[h][t], ex2f_(neghb * lg2f_(uu)), Ksum);
                        }
                        blc = fmaf(dqk[nt][c], dplL, fmaf(glkL, lg2f_(Ksum), mneg));
                    }
                    p = ex2f_(blc);
                }
                dqk[nt][c] = p;
            }
            int cl = wn*32 + nt*8 + 2*ra;
            float p00 = dqk[nt][0], p01 = dqk[nt][1];
            float p10 = dqk[nt][2], p11 = dqk[nt][3];
            if (diag) {
                if (row0 == cl) dws[row0] = p00; else if (row0 == cl+1) dws[row0] = p01;
                if (row0+8 == cl) dws[row0+8] = p10; else if (row0+8 == cl+1) dws[row0+8] = p11;
            }
            uint2 s0; s0.x = f2tf32(p00); s0.y = f2tf32(p01);
            uint2 s1; s1.x = f2tf32(p10); s1.y = f2tf32(p11);
            *(uint2*)(Ps + row0*68 + cl) = s0;
            *(uint2*)(Ps + (row0+8)*68 + cl) = s1;
        }
        __syncthreads();   // Ps visible

        // ---- PV MMAs (k=64; wn==1 adds ones-column for row-sum l) ----
        #pragma unroll
        for (int ks = 0; ks < 8; ++ks) {
            int kc = ks*8 + ra;
            const unsigned* pp_ = Ps + row0*68 + kc;
            unsigned pf[4] = {pp_[0], pp_[8*68], pp_[4], pp_[8*68+4]};
            #pragma unroll
            for (int nt = 0; nt < 5; ++nt) {
                if (nt == 4 && wn == 0) break;
                const unsigned* vp = Vs + (wn*32 + nt*8 + qa)*68 + kc;
                unsigned vf[2] = {vp[0], vp[4]};
                mma_tf32(apv[nt], pf, vf);
            }
        }
    }

    // ---- write partials (all at common scale 2^-M, no merge needed) ----
    int base = (h*72 + uidx)*64;
    #pragma unroll
    for (int nt = 0; nt < 4; ++nt) {
        int cl = wn*32 + nt*8 + 2*ra;
        float2 a0 = {apv[nt][0], apv[nt][1]};
        float2 a1 = {apv[nt][2], apv[nt][3]};
        *(float2*)(g_pacc + (size_t)(base + row0)*64 + cl) = a0;
        *(float2*)(g_pacc + (size_t)(base + row0 + 8)*64 + cl) = a1;
    }
    if (wn == 1 && ra == 0) {
        g_pl[base + row0]     = apv[4][0];
        g_pl[base + row0 + 8] = apv[4][2];
    }
    if (jt1 == it && tid < 64) g_dw[(h*16 + it)*64 + tid] = dws[tid];
}

// ---------------- combine partials -> g_y (same-scale: plain sums) ----------------
__global__ __launch_bounds__(256) void attn_combine() {
    int bid = blockIdx.x;
    int h = bid % H_N, it = bid / H_N;
    int i0 = it * 64;
    int nc = it/2 + 1;
    int tid = threadIdx.x;
    int row = tid >> 2;
    int c0 = (tid & 3) * 16;
    int b0 = (h*72 + c_off[it])*64 + row;

    float L = 0.f;
    for (int c = 0; c < nc; ++c) L += g_pl[b0 + c*64];
    float linv = 1.f / fmaxf(L, 1e-33f);
    float pii = g_dw[(h*16 + it)*64 + row] * linv;
    float alpha = g_c.alpha;
    float ca = 1.f - alpha;
    float cb = alpha / (1.f + pii);
    float outs = g_c.outs[h];

    for (int cc = 0; cc < 16; cc += 4) {
        float ax=0.f, ay=0.f, az=0.f, aw=0.f;
        for (int c = 0; c < nc; ++c) {
            float4 p = *(const float4*)(g_pacc + (size_t)(b0 + c*64)*64 + c0 + cc);
            ax += p.x; ay += p.y; az += p.z; aw += p.w;
        }
        float4 v = *(const float4*)(g_v + (size_t)(h*T_N + i0 + row)*D_N + c0 + cc);
        float4 o;
        float p0 = ax*linv, p1 = ay*linv, p2 = az*linv, p3 = aw*linv;
        o.x = outs * (ca*p0 + cb*(p0 + pii*v.x));
        o.y = outs * (ca*p1 + cb*(p1 + pii*v.y));
        o.z = outs * (ca*p2 + cb*(p2 + pii*v.z));
        o.w = outs * (ca*p3 + cb*(p3 + pii*v.w));
        *(float4*)(g_y + (size_t)(i0 + row)*C_N + h*D_N + c0 + cc) = o;
    }
}

// ---------------- launch ----------------
extern "C" void kernel_launch(void* const* d_in, const int* in_sizes, int n_in,
                              void* d_out, int out_size) {
    const float* x         = (const float*)d_in[0];
    const float* W_qkvg    = (const float*)d_in[1];
    const float* W_out     = (const float*)d_in[2];
    const float* lam       = (const float*)d_in[3];
    const float* log_tau   = (const float*)d_in[4];
    const float* logit_w   = (const float*)d_in[5];
    const float* beta      = (const float*)d_in[6];
    const float* out_scale = (const float*)d_in[7];
    const float* dp_scale  = (const float*)d_in[8];
    const float* logk_sc   = (const float*)d_in[9];
    const float* dt_logit  = (const float*)d_in[10];
    const float* gnw       = (const float*)d_in[11];
    float* out = (float*)d_out;

    float *y_p = nullptr, *op_p = nullptr;
    cudaGetSymbolAddress((void**)&y_p, g_y);
    cudaGetSymbolAddress((void**)&op_p, g_op);

    const int G64_SMEM = 2*STG64*4;
    cudaFuncSetAttribute(gemm_tf32_64, cudaFuncAttributeMaxDynamicSharedMemorySize, G64_SMEM);
    cudaFuncSetAttribute(attn_part, cudaFuncAttributeMaxDynamicSharedMemorySize, ATT_SMEM_BYTES);

    const_kernel<<<1, 32>>>(lam, log_tau, logit_w, beta, out_scale, dp_scale, logk_sc, dt_logit);
    gemm_tf32_64<<<dim3(3072/128, 1024/64), 256, G64_SMEM>>>(x, W_qkvg, nullptr, T_N, 4*C_N, C_N, C_N, 1);
    rmsnorm_g<<<(H_N*T_N*32)/256, 256>>>(gnw);
    attn_part<<<864, 256, ATT_SMEM_BYTES>>>();
    attn_combine<<<192, 256>>>();
    gemm_tf32_64<<<dim3(768/128, 1024/64, 3), 256, G64_SMEM>>>(y_p, W_out, op_p, T_N, C_N, C_N, 256, 0);
    addk_kernel<<<(T_N*C_N/4)/256, 256>>>(out);
}

// round 12
// speedup vs baseline: 1.7441x; 1.0007x over previous
#include <cuda_runtime.h>
#include <cuda_bf16.h>

#define T_N 1024
#define C_N 768
#define H_N 12
#define D_N 64
#define NT_N 8
#define LOG2E 1.4426950408889634f

// ---------------- scratch (static device globals; no allocation) ----------------
__device__ float g_q[H_N * T_N * D_N];       // [H][T][D]
__device__ float g_k[H_N * T_N * D_N];
__device__ float g_v[H_N * T_N * D_N];
__device__ float g_g[H_N * T_N * D_N];       // raw then rmsnormed+tf32-quantized g
__device__ float g_g2[H_N * T_N];            // ||ghat||^2 per (h,t)
__device__ float g_y[T_N * C_N];             // attention out, [T][C] layout
__device__ unsigned g_red[H_N][3];           // per-head max ||q||^2, ||k||^2, g2 (uint-ordered)
__device__ float g_op[3 * T_N * C_N];        // split-k partials for out projection

// split-j partials: 72 units per head (chunks of <=2 j-tiles), all at scale 2^-M
__device__ float g_pacc[H_N * 72 * 64 * 64]; // [h][unit][row][col]
__device__ float g_pl[H_N * 72 * 64];
__device__ float g_dw[H_N * 16 * 64];        // diag weights per (h,it,row)

// unit tables: 2-tile units first (heavy), then 1-tile remainders
__constant__ int c_uit[72] = {
    15,15,15,15,15,15,15,15, 14,14,14,14,14,14,14, 13,13,13,13,13,13,13,
    12,12,12,12,12,12, 11,11,11,11,11,11, 10,10,10,10,10, 9,9,9,9,9,
    8,8,8,8, 7,7,7,7, 6,6,6, 5,5,5, 4,4, 3,3, 2, 1,
    14,12,10,8,6,4,2,0};
__constant__ int c_uc[72] = {
    0,1,2,3,4,5,6,7, 0,1,2,3,4,5,6, 0,1,2,3,4,5,6,
    0,1,2,3,4,5, 0,1,2,3,4,5, 0,1,2,3,4, 0,1,2,3,4,
    0,1,2,3, 0,1,2,3, 0,1,2, 0,1,2, 0,1, 0,1, 0, 0,
    7,6,5,4,3,2,1,0};
__constant__ int c_off[16] = {0,1,2,4,6,9,12,16,20,25,30,36,42,49,56,64};

struct Consts {
    float inv4tau[H_N][NT_N];
    float wte[H_N][NT_N];
    float neghb[H_N];
    float dpl[H_N];           // lam * dp_scale/(8*0.8)
    float glk[H_N];           // (1-lam) * logk_scale * ln2
    float outs[H_N];
    float fA[H_N], fB[H_N], i4t0[H_N];
    int   fastf[H_N];
    float alpha;
};
__device__ Consts g_c;

__device__ __forceinline__ float ex2f_(float x){ float y; asm("ex2.approx.ftz.f32 %0, %1;":"=f"(y):"f"(x)); return y; }
__device__ __forceinline__ float lg2f_(float x){ float y; asm("lg2.approx.ftz.f32 %0, %1;":"=f"(y):"f"(x)); return y; }
__device__ __forceinline__ unsigned f2tf32(float x){ unsigned y; asm("cvt.rna.tf32.f32 %0, %1;":"=r"(y):"f"(x)); return y; }

__device__ __forceinline__ void mma_tf32(float* d, const unsigned* a, const unsigned* b) {
    asm volatile(
      "mma.sync.aligned.m16n8k8.row.col.f32.tf32.tf32.f32 "
      "{%0,%1,%2,%3}, {%4,%5,%6,%7}, {%8,%9}, {%0,%1,%2,%3};\n"
      : "+f"(d[0]), "+f"(d[1]), "+f"(d[2]), "+f"(d[3])
      : "r"(a[0]), "r"(a[1]), "r"(a[2]), "r"(a[3]), "r"(b[0]), "r"(b[1]));
}

// ---------------- constants precompute (parallel over heads; zero reduce cells) ----------------
__global__ void const_kernel(const float* lam_p, const float* log_tau,
                             const float* logit_w, const float* beta,
                             const float* out_scale, const float* dp_scale,
                             const float* logk_scale, const float* dt_logit) {
    int h = threadIdx.x;
    if (blockIdx.x != 0 || h >= H_N) return;
    float lam = lam_p[0];
    g_red[h][0] = 0u; g_red[h][1] = 0u; g_red[h][2] = 0u;
    float mx = -1e30f;
    for (int t = 0; t < NT_N; ++t) mx = fmaxf(mx, logit_w[h*NT_N+t]);
    float s = 0.f, e[NT_N];
    for (int t = 0; t < NT_N; ++t) { e[t] = expf(logit_w[h*NT_N+t]-mx); s += e[t]; }
    float W = 0.f;
    for (int t = 0; t < NT_N; ++t) { g_c.wte[h][t] = e[t]/s + 1e-12f; W += g_c.wte[h][t]; }
    for (int t = 0; t < NT_N; ++t) {
        float tau = fmaxf(expf(log_tau[h*NT_N+t]), 1e-6f);
        g_c.inv4tau[h][t] = 1.f/(4.f*tau);
    }
    float bc = fminf(fmaxf(beta[h], 0.5f), 2.5f);
    float neghb = -0.5f*bc;
    float dpc = dp_scale[h]/(8.0f*0.8f);
    float lks = logk_scale[h]*0.6931471805599453f;
    g_c.neghb[h] = neghb;
    g_c.dpl[h]   = lam*dpc;
    g_c.glk[h]   = (1.f-lam)*lks;
    g_c.outs[h]  = out_scale[h];
    int same = 1;
    for (int t = 1; t < NT_N; ++t) if (g_c.inv4tau[h][t] != g_c.inv4tau[h][0]) same = 0;
    g_c.fastf[h] = same;
    g_c.i4t0[h]  = g_c.inv4tau[h][0];
    g_c.fA[h]    = g_c.glk[h]*neghb;
    g_c.fB[h]    = g_c.glk[h]*log2f(W);
    if (h == 0) g_c.alpha = 0.1f/(1.f+expf(-dt_logit[0]));
}

// ---------------- tf32 GEMM 64x128, double-buffered, k-range, optional qkvg scatter ----------------
// launch_bounds(256,3): 3 CTAs/SM -> 384-CTA qkvg grid fits in ONE wave (444 slots)
#define GS 36
#define STG64 ((64+128)*GS)

__global__ __launch_bounds__(256, 3) void gemm_tf32_64(const float* __restrict__ A,
        const float* __restrict__ B, float* __restrict__ C, int M, int N, int Kst,
        int klen, int scatter) {
    extern __shared__ unsigned gsm[];
    int tid = threadIdx.x;
    int lane = tid & 31, w = tid >> 5;
    int wm = w >> 2, wn = w & 3;
    int m0 = blockIdx.y*64, n0 = blockIdx.x*128;
    int k0 = blockIdx.z*klen;
    int lr = tid >> 3, lc = (tid & 7)*4;
    const float* Ap = A + (size_t)(m0+lr)*Kst + k0 + lc;
    const float* Bp = B + (size_t)(n0+lr)*Kst + k0 + lc;

    float acc[2][4][4];
    #pragma unroll
    for (int i = 0; i < 2; ++i)
        #pragma unroll
        for (int j = 0; j < 4; ++j)
            #pragma unroll
            for (int v = 0; v < 4; ++v) acc[i][j][v] = 0.f;

    int qa = lane >> 2, ra = lane & 3;

    float4 pra[2], prb[4];
    #pragma unroll
    for (int p = 0; p < 2; ++p) pra[p] = *(const float4*)(Ap + (size_t)p*32*Kst);
    #pragma unroll
    for (int p = 0; p < 4; ++p) prb[p] = *(const float4*)(Bp + (size_t)p*32*Kst);
    {
        unsigned* As = gsm;
        unsigned* Bs = gsm + 64*GS;
        #pragma unroll
        for (int p = 0; p < 2; ++p) {
            unsigned* as = As + (lr + p*32)*GS + lc;
            as[0]=f2tf32(pra[p].x); as[1]=f2tf32(pra[p].y); as[2]=f2tf32(pra[p].z); as[3]=f2tf32(pra[p].w);
        }
        #pragma unroll
        for (int p = 0; p < 4; ++p) {
            unsigned* bs = Bs + (lr + p*32)*GS + lc;
            bs[0]=f2tf32(prb[p].x); bs[1]=f2tf32(prb[p].y); bs[2]=f2tf32(prb[p].z); bs[3]=f2tf32(prb[p].w);
        }
    }
    __syncthreads();
    int cur = 0;

    for (int kb = 0; kb < klen; kb += 32) {
        bool nxt = (kb + 32 < klen);
        if (nxt) {
            #pragma unroll
            for (int p = 0; p < 2; ++p) pra[p] = *(const float4*)(Ap + (size_t)p*32*Kst + kb + 32);
            #pragma unroll
            for (int p = 0; p < 4; ++p) prb[p] = *(const float4*)(Bp + (size_t)p*32*Kst + kb + 32);
        }
        unsigned* As = gsm + cur*STG64;
        unsigned* Bs = As + 64*GS;
        #pragma unroll
        for (int ks = 0; ks < 4; ++ks) {
            unsigned af[2][4], bf[4][2];
            #pragma unroll
            for (int mt = 0; mt < 2; ++mt) {
                const unsigned* p = As + (wm*32 + mt*16 + qa)*GS + ks*8 + ra;
                af[mt][0] = p[0];
                af[mt][1] = p[8*GS];
                af[mt][2] = p[4];
                af[mt][3] = p[8*GS + 4];
            }
            #pragma unroll
            for (int nt = 0; nt < 4; ++nt) {
                const unsigned* p = Bs + (wn*32 + nt*8 + qa)*GS + ks*8 + ra;
                bf[nt][0] = p[0];
                bf[nt][1] = p[4];
            }
            #pragma unroll
            for (int mt = 0; mt < 2; ++mt)
                #pragma unroll
                for (int nt = 0; nt < 4; ++nt)
                    mma_tf32(acc[mt][nt], af[mt], bf[nt]);
        }
        if (nxt) {
            unsigned* As2 = gsm + (cur^1)*STG64;
            unsigned* Bs2 = As2 + 64*GS;
            #pragma unroll
            for (int p = 0; p < 2; ++p) {
                unsigned* as = As2 + (lr + p*32)*GS + lc;
                as[0]=f2tf32(pra[p].x); as[1]=f2tf32(pra[p].y); as[2]=f2tf32(pra[p].z); as[3]=f2tf32(pra[p].w);
            }
            #pragma unroll
            for (int p = 0; p < 4; ++p) {
                unsigned* bs = Bs2 + (lr + p*32)*GS + lc;
                bs[0]=f2tf32(prb[p].x); bs[1]=f2tf32(prb[p].y); bs[2]=f2tf32(prb[p].z); bs[3]=f2tf32(prb[p].w);
            }
            __syncthreads();
            cur ^= 1;
        }
    }

    float* Cp = C + (size_t)blockIdx.z*M*N;
    #pragma unroll
    for (int mt = 0; mt < 2; ++mt) {
        int row = m0 + wm*32 + mt*16 + qa;
        #pragma unroll
        for (int nt = 0; nt < 4; ++nt) {
            float2 c0 = {acc[mt][nt][0], acc[mt][nt][1]};
            float2 c1 = {acc[mt][nt][2], acc[mt][nt][3]};
            if (scatter) {
                int colb = n0 + wn*32 + nt*8;      // section & head uniform per fragment
                int sec = colb / C_N;
                int hh = (colb % C_N) >> 6;
                int dd = (colb & 63) + ra*2;
                float* base = (sec == 0) ? g_q : (sec == 1) ? g_k : (sec == 2) ? g_v : g_g;
                *(float2*)(base + ((size_t)(hh*T_N + row)*D_N + dd)) = c0;
                *(float2*)(base + ((size_t)(hh*T_N + row + 8)*D_N + dd)) = c1;
            } else {
                int col = n0 + wn*32 + nt*8 + ra*2;
                *(float2*)(Cp + (size_t)row*N + col) = c0;
                *(float2*)(Cp + (size_t)(row+8)*N + col) = c1;
            }
        }
    }
}

// ---------------- split-k add: out = p0 + p1 + p2 ----------------
__global__ __launch_bounds__(256) void addk_kernel(float* __restrict__ out) {
    int i = blockIdx.x*256 + threadIdx.x;     // float4 index, grid exact
    const float4* p0 = (const float4*)g_op;
    const float4* p1 = (const float4*)(g_op + T_N*C_N);
    const float4* p2 = (const float4*)(g_op + 2*T_N*C_N);
    float4 a = p0[i], b = p1[i], c = p2[i];
    float4 o;
    o.x = a.x + b.x + c.x;
    o.y = a.y + b.y + c.y;
    o.z = a.z + b.z + c.z;
    o.w = a.w + b.w + c.w;
    ((float4*)out)[i] = o;
}

// ---------------- rmsnorm g in place (quantize to tf32) + g2 + fused norm maxes ----------------
__global__ __launch_bounds__(256) void rmsnorm_g(const float* __restrict__ gnw) {
    __shared__ float smax[3][8];
    int gw = (blockIdx.x*256 + threadIdx.x) >> 5;   // row 0..12287, grid exact
    int lane = threadIdx.x & 31;
    int wid = threadIdx.x >> 5;
    int h = gw >> 10;
    float* p = g_g + (size_t)gw*D_N + lane*2;
    float2 gv = *(float2*)p;
    float ss = gv.x*gv.x + gv.y*gv.y;
    #pragma unroll
    for (int m = 16; m; m >>= 1) ss += __shfl_xor_sync(0xffffffffu, ss, m);
    float r = rsqrtf(ss*(1.0f/D_N) + 1e-6f);
    float2 wv = *(const float2*)(gnw + lane*2);
    float q0 = __uint_as_float(f2tf32(gv.x*r*wv.x));
    float q1 = __uint_as_float(f2tf32(gv.y*r*wv.y));
    float2 gq = {q0, q1};
    *(float2*)p = gq;
    float2 qv2 = *(const float2*)(g_q + (size_t)gw*D_N + lane*2);
    float2 kv2 = *(const float2*)(g_k + (size_t)gw*D_N + lane*2);
    float s2 = q0*q0 + q1*q1;
    float sq = qv2.x*qv2.x + qv2.y*qv2.y;
    float sk = kv2.x*kv2.x + kv2.y*kv2.y;
    #pragma unroll
    for (int m = 16; m; m >>= 1) {
        s2 += __shfl_xor_sync(0xffffffffu, s2, m);
        sq += __shfl_xor_sync(0xffffffffu, sq, m);
        sk += __shfl_xor_sync(0xffffffffu, sk, m);
    }
    if (lane == 0) {
        g_g2[gw] = s2;
        smax[0][wid] = sq; smax[1][wid] = sk; smax[2][wid] = s2;
    }
    __syncthreads();
    if (threadIdx.x < 3) {
        float mx = 0.f;
        #pragma unroll
        for (int i = 0; i < 8; ++i) mx = fmaxf(mx, smax[threadIdx.x][i]);
        atomicMax(&g_red[h][threadIdx.x], __float_as_uint(mx));
    }
}

// ---------------- split-j flash attention partial (fixed-max, no online softmax) ----------------
#define QS_O   0
#define GI_O   4352
#define KS_O   8704
#define GJ_O   13056
#define VS_O   17408            // 72 rows x 68 (row 64 = ones for row-sum, 65-71 zero)
#define PS_O   22304
#define G2I_O  26656
#define G2J_O  26720
#define DWS_O  26784
#define ATT_SMEM_WORDS 26848
#define ATT_SMEM_BYTES (ATT_SMEM_WORDS*4)

__global__ __launch_bounds__(256, 2) void attn_part() {
    extern __shared__ unsigned smu[];
    float* smf = (float*)smu;
    unsigned* Qs  = smu + QS_O;          // [64][68] tf32
    unsigned* Gis = smu + GI_O;          // [64][68] tf32 (pre-quantized g)
    unsigned* Ks  = smu + KS_O;
    unsigned* Gjs = smu + GJ_O;
    unsigned* Vs  = smu + VS_O;          // [72][68]: d rows 0-63, ones row 64
    unsigned* Ps  = smu + PS_O;
    float* g2i_s = smf + G2I_O;
    float* g2j_s = smf + G2J_O;
    float* dws   = smf + DWS_O;

    int bid = blockIdx.x;
    int h = bid % H_N;
    int u = bid / H_N;
    int it = c_uit[u], cch = c_uc[u];
    int i0 = it * 64;
    int jt0 = cch*2, jt1 = min(jt0+1, it);
    int uidx = c_off[it] + cch;
    int tid = threadIdx.x;
    int lane = tid & 31, w = tid >> 5;
    int wm = w >> 1, wn = w & 1;
    int qa = lane >> 2, ra = lane & 3;
    int row0 = wm*16 + qa;

    int fast = g_c.fastf[h];
    float i4t0 = g_c.i4t0[h];
    float neghb = g_c.neghb[h];

    // ---- derive safe max M from reduced norms (inline, few flops) ----
    float M2;
    {
        float mq = __uint_as_float(g_red[h][0]);
        float mk = __uint_as_float(g_red[h][1]);
        float mg = __uint_as_float(g_red[h][2]);
        float dplL_ = g_c.dpl[h]*LOG2E;
        float bqk = fabsf(dplL_)*sqrtf(mq*mk);
        float smax = 4.f*mg + 1.f;
        float kmax;
        if (fast) {
            float a = g_c.fA[h]*LOG2E, b = g_c.fB[h]*LOG2E;
            float t1 = fmaf(a, log2f(fmaf(smax, i4t0, 1.f)), b);
            kmax = fmaxf(t1, b);
        } else {
            float glkL_ = g_c.glk[h]*LOG2E;
            float W = 0.f, Kmin = 0.f;
            #pragma unroll
            for (int t = 0; t < NT_N; ++t) {
                W += g_c.wte[h][t];
                Kmin += g_c.wte[h][t]*powf(fmaf(smax, g_c.inv4tau[h][t], 1.f), neghb);
            }
            kmax = fmaxf(glkL_*log2f(W), glkL_*log2f(Kmin));
        }
        M2 = bqk + kmax + 1.f;
    }
    float dplL = g_c.dpl[h]*LOG2E;
    float fAL  = g_c.fA[h]*LOG2E;
    float fBM  = g_c.fB[h]*LOG2E - M2;
    float glkL = g_c.glk[h]*LOG2E;
    float mneg = -M2;

    const float* qg  = g_q + (size_t)(h*T_N + i0)*D_N;
    const float* gig = g_g + (size_t)(h*T_N + i0)*D_N;
    #pragma unroll
    for (int p = 0; p < 4; ++p) {
        int e = tid + p*256;
        int r = e >> 4, dc = (e & 15)*4;
        float4 a = *(const float4*)(qg + r*D_N + dc);
        uint4 ua; ua.x=f2tf32(a.x); ua.y=f2tf32(a.y); ua.z=f2tf32(a.z); ua.w=f2tf32(a.w);
        *(uint4*)(Qs + r*68 + dc) = ua;
        float4 b = *(const float4*)(gig + r*D_N + dc);
        uint4 ub; ub.x=__float_as_uint(b.x); ub.y=__float_as_uint(b.y);
        ub.z=__float_as_uint(b.z); ub.w=__float_as_uint(b.w);   // already tf32-quantized
        *(uint4*)(Gis + r*68 + dc) = ub;
    }
    if (tid < 64) g2i_s[tid] = g_g2[h*T_N + i0 + tid];
    // ones row (64) + zero rows (65-71) of Vs — written once, never overwritten
    for (int z = tid; z < 8*68; z += 256)
        Vs[64*68 + z] = (z < 64) ? f2tf32(1.f) : 0u;

    float apv[5][4];
    #pragma unroll
    for (int nt = 0; nt < 5; ++nt)
        #pragma unroll
        for (int c = 0; c < 4; ++c) apv[nt][c] = 0.f;

    for (int jt = jt0; jt <= jt1; ++jt) {
        int j0 = jt*64;
        __syncthreads();   // prev tile's Ps/Vs reads done
        const float* kg  = g_k + (size_t)(h*T_N + j0)*D_N;
        const float* gjg = g_g + (size_t)(h*T_N + j0)*D_N;
        const float* vg  = g_v + (size_t)(h*T_N + j0)*D_N;
        #pragma unroll
        for (int p = 0; p < 4; ++p) {
            int e = tid + p*256;
            int r = e >> 4, dc = (e & 15)*4;
            float4 a = *(const float4*)(kg + r*D_N + dc);
            uint4 ua; ua.x=f2tf32(a.x); ua.y=f2tf32(a.y); ua.z=f2tf32(a.z); ua.w=f2tf32(a.w);
            *(uint4*)(Ks + r*68 + dc) = ua;
            float4 b = *(const float4*)(gjg + r*D_N + dc);
            uint4 ub; ub.x=__float_as_uint(b.x); ub.y=__float_as_uint(b.y);
            ub.z=__float_as_uint(b.z); ub.w=__float_as_uint(b.w);
            *(uint4*)(Gjs + r*68 + dc) = ub;
            int j = e & 63, dg = (e >> 6)*4;
            float4 v = *(const float4*)(vg + j*D_N + dg);
            Vs[(dg+0)*68 + j] = f2tf32(v.x);
            Vs[(dg+1)*68 + j] = f2tf32(v.y);
            Vs[(dg+2)*68 + j] = f2tf32(v.z);
            Vs[(dg+3)*68 + j] = f2tf32(v.w);
        }
        if (tid < 64) g2j_s[tid] = g_g2[h*T_N + j0 + tid];
        __syncthreads();

        // ---- QK + GG MMAs ----
        float dqk[4][4], dgg[4][4];
        #pragma unroll
        for (int nt = 0; nt < 4; ++nt)
            #pragma unroll
            for (int c = 0; c < 4; ++c) { dqk[nt][c] = 0.f; dgg[nt][c] = 0.f; }

        #pragma unroll
        for (int ks = 0; ks < 8; ++ks) {
            int kc = ks*8 + ra;
            const unsigned* qp = Qs + row0*68 + kc;
            unsigned af[4] = {qp[0], qp[8*68], qp[4], qp[8*68+4]};
            const unsigned* gp = Gis + row0*68 + kc;
            unsigned gf[4] = {gp[0], gp[8*68], gp[4], gp[8*68+4]};
            #pragma unroll
            for (int nt = 0; nt < 4; ++nt) {
                int nb = wn*32 + nt*8 + qa;
                const unsigned* kp = Ks + nb*68 + kc;
                unsigned bf[2] = {kp[0], kp[4]};
                const unsigned* gjp = Gjs + nb*68 + kc;
                unsigned bgf[2] = {gjp[0], gjp[4]};
                mma_tf32(dqk[nt], af, bf);
                mma_tf32(dgg[nt], gf, bgf);
            }
        }

        // ---- epilogue: p = 2^(score - M), no running max, no row exchange ----
        int diag = (jt == it);
        #pragma unroll
        for (int nt = 0; nt < 4; ++nt) {
            #pragma unroll
            for (int c = 0; c < 4; ++c) {
                int rh = c >> 1, pp = c & 1;
                int rl = row0 + rh*8;
                int cl = wn*32 + nt*8 + 2*ra + pp;
                float p = 0.f;
                if (j0 + cl <= i0 + rl) {
                    float s = fmaxf(g2i_s[rl] + g2j_s[cl] - 2.f*dgg[nt][c], 0.f);
                    float blc;
                    if (fast) {
                        blc = fmaf(dqk[nt][c], dplL, fmaf(fAL, lg2f_(fmaf(s, i4t0, 1.f)), fBM));
                    } else {
                        float Ksum = 0.f;
                        #pragma unroll
                        for (int t = 0; t < 8; ++t) {
                            float uu = fmaf(s, g_c.inv4tau[h][t], 1.f);
                            Ksum = fmaf(g_c.wte[h][t], ex2f_(neghb * lg2f_(uu)), Ksum);
                        }
                        blc = fmaf(dqk[nt][c], dplL, fmaf(glkL, lg2f_(Ksum), mneg));
                    }
                    p = ex2f_(blc);
                }
                dqk[nt][c] = p;
            }
            int cl = wn*32 + nt*8 + 2*ra;
            float p00 = dqk[nt][0], p01 = dqk[nt][1];
            float p10 = dqk[nt][2], p11 = dqk[nt][3];
            if (diag) {
                if (row0 == cl) dws[row0] = p00; else if (row0 == cl+1) dws[row0] = p01;
                if (row0+8 == cl) dws[row0+8] = p10; else if (row0+8 == cl+1) dws[row0+8] = p11;
            }
            uint2 s0; s0.x = f2tf32(p00); s0.y = f2tf32(p01);
            uint2 s1; s1.x = f2tf32(p10); s1.y = f2tf32(p11);
            *(uint2*)(Ps + row0*68 + cl) = s0;
            *(uint2*)(Ps + (row0+8)*68 + cl) = s1;
        }
        __syncthreads();   // Ps visible

        // ---- PV MMAs (k=64; wn==1 adds ones-column for row-sum l) ----
        #pragma unroll
        for (int ks = 0; ks < 8; ++ks) {
            int kc = ks*8 + ra;
            const unsigned* pp_ = Ps + row0*68 + kc;
            unsigned pf[4] = {pp_[0], pp_[8*68], pp_[4], pp_[8*68+4]};
            #pragma unroll
            for (int nt = 0; nt < 5; ++nt) {
                if (nt == 4 && wn == 0) break;
                const unsigned* vp = Vs + (wn*32 + nt*8 + qa)*68 + kc;
                unsigned vf[2] = {vp[0], vp[4]};
                mma_tf32(apv[nt], pf, vf);
            }
        }
    }

    // ---- write partials (all at common scale 2^-M, no merge needed) ----
    int base = (h*72 + uidx)*64;
    #pragma unroll
    for (int nt = 0; nt < 4; ++nt) {
        int cl = wn*32 + nt*8 + 2*ra;
        float2 a0 = {apv[nt][0], apv[nt][1]};
        float2 a1 = {apv[nt][2], apv[nt][3]};
        *(float2*)(g_pacc + (size_t)(base + row0)*64 + cl) = a0;
        *(float2*)(g_pacc + (size_t)(base + row0 + 8)*64 + cl) = a1;
    }
    if (wn == 1 && ra == 0) {
        g_pl[base + row0]     = apv[4][0];
        g_pl[base + row0 + 8] = apv[4][2];
    }
    if (jt1 == it && tid < 64) g_dw[(h*16 + it)*64 + tid] = dws[tid];
}

// ---------------- combine partials -> g_y (same-scale: plain sums) ----------------
__global__ __launch_bounds__(256) void attn_combine() {
    int bid = blockIdx.x;
    int h = bid % H_N, it = bid / H_N;
    int i0 = it * 64;
    int nc = it/2 + 1;
    int tid = threadIdx.x;
    int row = tid >> 2;
    int c0 = (tid & 3) * 16;
    int b0 = (h*72 + c_off[it])*64 + row;

    float L = 0.f;
    for (int c = 0; c < nc; ++c) L += g_pl[b0 + c*64];
    float linv = 1.f / fmaxf(L, 1e-33f);
    float pii = g_dw[(h*16 + it)*64 + row] * linv;
    float alpha = g_c.alpha;
    float ca = 1.f - alpha;
    float cb = alpha / (1.f + pii);
    float outs = g_c.outs[h];

    for (int cc = 0; cc < 16; cc += 4) {
        float ax=0.f, ay=0.f, az=0.f, aw=0.f;
        for (int c = 0; c < nc; ++c) {
            float4 p = *(const float4*)(g_pacc + (size_t)(b0 + c*64)*64 + c0 + cc);
            ax += p.x; ay += p.y; az += p.z; aw += p.w;
        }
        float4 v = *(const float4*)(g_v + (size_t)(h*T_N + i0 + row)*D_N + c0 + cc);
        float4 o;
        float p0 = ax*linv, p1 = ay*linv, p2 = az*linv, p3 = aw*linv;
        o.x = outs * (ca*p0 + cb*(p0 + pii*v.x));
        o.y = outs * (ca*p1 + cb*(p1 + pii*v.y));
        o.z = outs * (ca*p2 + cb*(p2 + pii*v.z));
        o.w = outs * (ca*p3 + cb*(p3 + pii*v.w));
        *(float4*)(g_y + (size_t)(i0 + row)*C_N + h*D_N + c0 + cc) = o;
    }
}

// ---------------- launch ----------------
extern "C" void kernel_launch(void* const* d_in, const int* in_sizes, int n_in,
                              void* d_out, int out_size) {
    const float* x         = (const float*)d_in[0];
    const float* W_qkvg    = (const float*)d_in[1];
    const float* W_out     = (const float*)d_in[2];
    const float* lam       = (const float*)d_in[3];
    const float* log_tau   = (const float*)d_in[4];
    const float* logit_w   = (const float*)d_in[5];
    const float* beta      = (const float*)d_in[6];
    const float* out_scale = (const float*)d_in[7];
    const float* dp_scale  = (const float*)d_in[8];
    const float* logk_sc   = (const float*)d_in[9];
    const float* dt_logit  = (const float*)d_in[10];
    const float* gnw       = (const float*)d_in[11];
    float* out = (float*)d_out;

    float *y_p = nullptr, *op_p = nullptr;
    cudaGetSymbolAddress((void**)&y_p, g_y);
    cudaGetSymbolAddress((void**)&op_p, g_op);

    const int G64_SMEM = 2*STG64*4;
    cudaFuncSetAttribute(gemm_tf32_64, cudaFuncAttributeMaxDynamicSharedMemorySize, G64_SMEM);
    cudaFuncSetAttribute(attn_part, cudaFuncAttributeMaxDynamicSharedMemorySize, ATT_SMEM_BYTES);

    const_kernel<<<1, 32>>>(lam, log_tau, logit_w, beta, out_scale, dp_scale, logk_sc, dt_logit);
    gemm_tf32_64<<<dim3(3072/128, 1024/64), 256, G64_SMEM>>>(x, W_qkvg, nullptr, T_N, 4*C_N, C_N, C_N, 1);
    rmsnorm_g<<<(H_N*T_N*32)/256, 256>>>(gnw);
    attn_part<<<864, 256, ATT_SMEM_BYTES>>>();
    attn_combine<<<192, 256>>>();
    gemm_tf32_64<<<dim3(768/128, 1024/64, 3), 256, G64_SMEM>>>(y_p, W_out, op_p, T_N, C_N, C_N, 256, 0);
    addk_kernel<<<(T_N*C_N/4)/256, 256>>>(out);
}